// round 10
// baseline (speedup 1.0000x reference)
#include <cuda_runtime.h>
#include <cuda_fp16.h>
#include <math.h>
#include <stdint.h>

#define NN 65536
#define FF 1024
#define BK 64
#define NCHUNK (FF / BK)     // 16
#define BM 128
#define BN 128
#define NTHREADS 512
#define STAGES 3

// per-stage smem: A hi/lo + B hi/lo, each 128 rows x 64 halfs (16KB)
#define OFF_AH 0
#define OFF_AL 16384
#define OFF_BH 32768
#define OFF_BL 49152
#define STAGE_BYTES 65536
#define DYN_SMEM (STAGES * STAGE_BYTES)   // 192 KB

// ---------------------------------------------------------------------------
// Device scratch
// ---------------------------------------------------------------------------
__device__ __half g_in0h[(size_t)NN * FF], g_in0l[(size_t)NN * FF]; // query split
__device__ __half g_in1h[(size_t)NN * FF], g_in1l[(size_t)NN * FF]; // key split
__device__ __half g_w0h[FF * FF], g_w0l[FF * FF];
__device__ __half g_w1h[FF * FF], g_w1l[FF * FF];
__device__ __half g_wah[FF * FF], g_wal[FF * FF];
__device__ float  g_kenc[(size_t)NN * FF];                      // fp32 k_enc
__device__ __half g_qench[(size_t)NN * FF], g_qencl[(size_t)NN * FF];
__device__ float  g_epart[8 * NN];
__device__ float  g_energy[NN], g_weights[NN];
__device__ float  g_ctxpart[256 * FF];

// ---------------------------------------------------------------------------
// PTX helpers (sm_80-class, arch-generic)
// ---------------------------------------------------------------------------
__device__ __forceinline__ uint32_t smem_u32(const void* p) {
    uint32_t a;
    asm("{ .reg .u64 t; cvta.to.shared.u64 t, %1; cvt.u32.u64 %0, t; }"
        : "=r"(a) : "l"(p));
    return a;
}

#define CP_ASYNC16(saddr, gptr) \
    asm volatile("cp.async.cg.shared.global [%0], [%1], 16;" \
                 :: "r"(saddr), "l"(gptr))
#define CP_COMMIT() asm volatile("cp.async.commit_group;" ::: "memory")
#define CP_WAIT0()  asm volatile("cp.async.wait_group 0;" ::: "memory")
#define CP_WAIT1()  asm volatile("cp.async.wait_group 1;" ::: "memory")

__device__ __forceinline__ void ldsm4(uint32_t* r, uint32_t a) {
    asm volatile("ldmatrix.sync.aligned.m8n8.x4.shared.b16 {%0,%1,%2,%3}, [%4];"
                 : "=r"(r[0]), "=r"(r[1]), "=r"(r[2]), "=r"(r[3]) : "r"(a));
}

__device__ __forceinline__ void mma16816(float* d, const uint32_t* a,
                                         uint32_t b0, uint32_t b1) {
    asm volatile(
        "mma.sync.aligned.m16n8k16.row.col.f32.f16.f16.f32 "
        "{%0,%1,%2,%3}, {%4,%5,%6,%7}, {%8,%9}, {%0,%1,%2,%3};"
        : "+f"(d[0]), "+f"(d[1]), "+f"(d[2]), "+f"(d[3])
        : "r"(a[0]), "r"(a[1]), "r"(a[2]), "r"(a[3]), "r"(b0), "r"(b1));
}

// 128B rows (8 chunks of 16B): chunk' = c ^ (r&7); conflict-free ldmatrix.
__device__ __forceinline__ uint32_t swz(int r, int c) {
    return (uint32_t)(r * 128 + ((c ^ (r & 7)) << 4));
}

__device__ __forceinline__ uint32_t pack_hi2(float a, float b) {
    __half2 h = __halves2half2(__float2half_rn(a), __float2half_rn(b));
    return *(uint32_t*)&h;
}
__device__ __forceinline__ uint32_t pack_lo2(float a, float b) {
    __half ha = __float2half_rn(a), hb = __float2half_rn(b);
    __half2 l = __halves2half2(__float2half_rn(a - __half2float(ha)),
                               __float2half_rn(b - __half2float(hb)));
    return *(uint32_t*)&l;
}

// ---------------------------------------------------------------------------
// Split fp32 -> (hi, lo) fp16. 4 float4 per thread (MLP=4).
// ---------------------------------------------------------------------------
__global__ __launch_bounds__(256) void split_kernel(
    const float4* __restrict__ x, uint4* __restrict__ hi,
    uint4* __restrict__ lo, int n4)
{
    const int i0 = (blockIdx.x * 256 + threadIdx.x) * 4;
    float4 v0 = x[i0], v1 = x[i0 + 1], v2 = x[i0 + 2], v3 = x[i0 + 3];

    uint4 h0, h1, l0, l1;
    h0.x = pack_hi2(v0.x, v0.y); h0.y = pack_hi2(v0.z, v0.w);
    h0.z = pack_hi2(v1.x, v1.y); h0.w = pack_hi2(v1.z, v1.w);
    h1.x = pack_hi2(v2.x, v2.y); h1.y = pack_hi2(v2.z, v2.w);
    h1.z = pack_hi2(v3.x, v3.y); h1.w = pack_hi2(v3.z, v3.w);
    l0.x = pack_lo2(v0.x, v0.y); l0.y = pack_lo2(v0.z, v0.w);
    l0.z = pack_lo2(v1.x, v1.y); l0.w = pack_lo2(v1.z, v1.w);
    l1.x = pack_lo2(v2.x, v2.y); l1.y = pack_lo2(v2.z, v2.w);
    l1.z = pack_lo2(v3.x, v3.y); l1.w = pack_lo2(v3.z, v3.w);

    hi[i0 >> 1] = h0; hi[(i0 >> 1) + 1] = h1;
    lo[i0 >> 1] = l0; lo[(i0 >> 1) + 1] = l1;
}

// ---------------------------------------------------------------------------
// Mainloop: 512 threads, 16 warps (4/SMSP), warp tile 32x32, fp16x3.
// BK=64, 3-stage cp.async pipeline, 1 barrier per chunk.
// ---------------------------------------------------------------------------
__device__ __forceinline__ void mma_mainloop(
    const __half* __restrict__ Ah, const __half* __restrict__ Al,
    const __half* __restrict__ Bh, const __half* __restrict__ Bl,
    char* dsm, int rowBase, int colBase, int tid, float acc[2][4][4])
{
    const int lane = tid & 31;
    const int w = tid >> 5, wm = w >> 2, wn = w & 3;
    const uint32_t sbase = smem_u32(dsm);

#pragma unroll
    for (int mt = 0; mt < 2; mt++)
#pragma unroll
        for (int nt = 0; nt < 4; nt++)
#pragma unroll
            for (int q = 0; q < 4; q++) acc[mt][nt][q] = 0.0f;

    const int a_r0 = wm * 32 + (lane & 15);
    const int a_ch = lane >> 4;
    const int b_r0 = wn * 32 + (lane & 7) + ((lane & 16) >> 1);
    const int b_ch = (lane >> 3) & 1;

    // stage load: A/B tiles 128 rows x 8 ck = 1024 slots each; 2 per thread
    auto load_stage = [&](int c, int slot) {
        const int k0 = c * BK;
        const uint32_t sb = sbase + slot * STAGE_BYTES;
#pragma unroll
        for (int i = 0; i < 2; i++) {
            const int id = tid + i * NTHREADS;     // 0..1023
            const int r = id >> 3, ck = id & 7;
            const uint32_t so = swz(r, ck);
            const size_t ga = (size_t)(rowBase + r) * FF + k0 + ck * 8;
            const size_t gb = (size_t)(colBase + r) * FF + k0 + ck * 8;
            CP_ASYNC16(sb + OFF_AH + so, Ah + ga);
            CP_ASYNC16(sb + OFF_AL + so, Al + ga);
            CP_ASYNC16(sb + OFF_BH + so, Bh + gb);
            CP_ASYNC16(sb + OFF_BL + so, Bl + gb);
        }
    };

    load_stage(0, 0); CP_COMMIT();
    load_stage(1, 1); CP_COMMIT();

    int s = 0;
    for (int c = 0; c < NCHUNK; c++) {
        if (c + 1 < NCHUNK) { CP_WAIT1(); } else { CP_WAIT0(); }
        __syncthreads();        // stage c visible; prior compute (slot reuse) done
        if (c + 2 < NCHUNK) {
            int sl = s + 2; if (sl >= STAGES) sl -= STAGES;
            load_stage(c + 2, sl);
            CP_COMMIT();
        }
        const uint32_t sb = sbase + s * STAGE_BYTES;

#pragma unroll
        for (int kk = 0; kk < 4; kk++) {
            uint32_t ah[2][4], al[2][4], bh[2][4], bl[2][4];
#pragma unroll
            for (int mt = 0; mt < 2; mt++) {
                const uint32_t so = swz(a_r0 + mt * 16, kk * 2 + a_ch);
                ldsm4(ah[mt], sb + OFF_AH + so);
                ldsm4(al[mt], sb + OFF_AL + so);
            }
#pragma unroll
            for (int p = 0; p < 2; p++) {
                const uint32_t so = swz(b_r0 + p * 16, kk * 2 + b_ch);
                ldsm4(bh[p], sb + OFF_BH + so);
                ldsm4(bl[p], sb + OFF_BL + so);
            }
#pragma unroll
            for (int mt = 0; mt < 2; mt++)
#pragma unroll
                for (int nt = 0; nt < 4; nt++) {
                    const int p = nt >> 1, o = (nt & 1) * 2;
                    mma16816(acc[mt][nt], ah[mt], bh[p][o], bh[p][o + 1]);
                    mma16816(acc[mt][nt], ah[mt], bl[p][o], bl[p][o + 1]);
                    mma16816(acc[mt][nt], al[mt], bh[p][o], bh[p][o + 1]);
                }
        }
        if (++s == STAGES) s = 0;
    }
}

// ---------------------------------------------------------------------------
// Fused GEMM1+GEMM2 (blockIdx.z): z=0 -> kenc fp32; z=1 -> qenc split hi/lo
// ---------------------------------------------------------------------------
__global__ __launch_bounds__(NTHREADS, 1) void gemm_enc2(
    const __half* __restrict__ A0h, const __half* __restrict__ A0l,
    const __half* __restrict__ B0h, const __half* __restrict__ B0l,
    const float* __restrict__ bias0,
    const __half* __restrict__ A1h, const __half* __restrict__ A1l,
    const __half* __restrict__ B1h, const __half* __restrict__ B1l,
    const float* __restrict__ bias1,
    __half* __restrict__ O1h, __half* __restrict__ O1l)
{
    extern __shared__ __align__(1024) char dsm[];
    const int tid = threadIdx.x;
    const int rowBase = blockIdx.y * BM;
    const int colBase = blockIdx.x * BN;
    const int z = blockIdx.z;

    const __half* Ah = z ? A1h : A0h;
    const __half* Al = z ? A1l : A0l;
    const __half* Bh = z ? B1h : B0h;
    const __half* Bl = z ? B1l : B0l;
    const float* bias = z ? bias1 : bias0;

    float acc[2][4][4];
    mma_mainloop(Ah, Al, Bh, Bl, dsm, rowBase, colBase, tid, acc);

    const int lane = tid & 31;
    const int w = tid >> 5, wm = w >> 2, wn = w & 3;

#pragma unroll
    for (int nt = 0; nt < 4; nt++) {
        const int col0 = colBase + wn * 32 + nt * 8 + 2 * (lane & 3);
        const float2 bb = *(const float2*)&bias[col0];
#pragma unroll
        for (int mt = 0; mt < 2; mt++) {
            const int row0 = rowBase + wm * 32 + mt * 16 + (lane >> 2);
#pragma unroll
            for (int h = 0; h < 2; h++) {
                const int row = row0 + h * 8;
                const float v0 = fmaxf(acc[mt][nt][2 * h]     + bb.x, 0.0f);
                const float v1 = fmaxf(acc[mt][nt][2 * h + 1] + bb.y, 0.0f);
                if (z == 0) {
                    *(float2*)&g_kenc[(size_t)row * FF + col0] = make_float2(v0, v1);
                } else {
                    __half h0 = __float2half_rn(v0), h1 = __float2half_rn(v1);
                    __half l0 = __float2half_rn(v0 - __half2float(h0));
                    __half l1 = __float2half_rn(v1 - __half2float(h1));
                    *(__half2*)&O1h[(size_t)row * FF + col0] = __halves2half2(h0, h1);
                    *(__half2*)&O1l[(size_t)row * FF + col0] = __halves2half2(l0, l1);
                }
            }
        }
    }
}

// ---------------------------------------------------------------------------
// GEMM3: attn = qenc @ Wa^T + ba, fused energy-partial epilogue
// ---------------------------------------------------------------------------
__global__ __launch_bounds__(NTHREADS, 1) void gemm_energy(
    const __half* __restrict__ Ah, const __half* __restrict__ Al,
    const __half* __restrict__ Bh, const __half* __restrict__ Bl,
    const float* __restrict__ ba)
{
    extern __shared__ __align__(1024) char dsm[];
    const int tid = threadIdx.x;
    const int rowBase = blockIdx.y * BM;
    const int colBase = blockIdx.x * BN;

    float acc[2][4][4];
    mma_mainloop(Ah, Al, Bh, Bl, dsm, rowBase, colBase, tid, acc);

    const int lane = tid & 31;
    const int w = tid >> 5, wm = w >> 2, wn = w & 3;

    float er[2][2];
#pragma unroll
    for (int mt = 0; mt < 2; mt++) { er[mt][0] = 0.0f; er[mt][1] = 0.0f; }

#pragma unroll
    for (int nt = 0; nt < 4; nt++) {
        const int col0 = colBase + wn * 32 + nt * 8 + 2 * (lane & 3);
        const float2 bb = *(const float2*)&ba[col0];
#pragma unroll
        for (int mt = 0; mt < 2; mt++) {
            const int row0 = rowBase + wm * 32 + mt * 16 + (lane >> 2);
#pragma unroll
            for (int h = 0; h < 2; h++) {
                const int row = row0 + h * 8;
                const float2 kk2 = *(const float2*)&g_kenc[(size_t)row * FF + col0];
                const float v0 = acc[mt][nt][2 * h]     + bb.x;
                const float v1 = acc[mt][nt][2 * h + 1] + bb.y;
                er[mt][h] += v0 * kk2.x + v1 * kk2.y;
            }
        }
    }

#pragma unroll
    for (int mt = 0; mt < 2; mt++) {
#pragma unroll
        for (int h = 0; h < 2; h++) {
            er[mt][h] += __shfl_xor_sync(0xffffffffu, er[mt][h], 1);
            er[mt][h] += __shfl_xor_sync(0xffffffffu, er[mt][h], 2);
        }
    }

    float* e_sm = (float*)dsm;   // [4 wn][128 rows]
    __syncthreads();
    if ((lane & 3) == 0) {
        const int rl0 = wm * 32 + (lane >> 2);
#pragma unroll
        for (int mt = 0; mt < 2; mt++) {
            e_sm[wn * 128 + rl0 + mt * 16]     = er[mt][0];
            e_sm[wn * 128 + rl0 + mt * 16 + 8] = er[mt][1];
        }
    }
    __syncthreads();
    if (tid < 128) {
        float e = e_sm[tid] + e_sm[128 + tid] + e_sm[256 + tid] + e_sm[384 + tid];
        g_epart[blockIdx.x * NN + rowBase + tid] = e;
    }
}

// ---------------------------------------------------------------------------
// Softmax with fused partial-reduce
// ---------------------------------------------------------------------------
__global__ __launch_bounds__(1024) void softmax_k()
{
    __shared__ float red[1024];
    const int t = threadIdx.x;

    float m = -1e30f;
    for (int i = t; i < NN; i += 1024) {
        float e = 0.0f;
#pragma unroll
        for (int p = 0; p < 8; p++) e += g_epart[p * NN + i];
        g_energy[i] = e;
        m = fmaxf(m, e);
    }
    red[t] = m;
    __syncthreads();
    for (int s = 512; s > 0; s >>= 1) {
        if (t < s) red[t] = fmaxf(red[t], red[t + s]);
        __syncthreads();
    }
    const float mx = red[0];
    __syncthreads();

    float sum = 0.0f;
    for (int i = t; i < NN; i += 1024) {
        const float w = expf(g_energy[i] - mx);
        g_weights[i] = w;
        sum += w;
    }
    red[t] = sum;
    __syncthreads();
    for (int s = 512; s > 0; s >>= 1) {
        if (t < s) red[t] += red[t + s];
        __syncthreads();
    }
    const float invZ = 1.0f / red[0];
    for (int i = t; i < NN; i += 1024) g_weights[i] *= invZ;
}

__global__ __launch_bounds__(256) void ctx_partial(const float* __restrict__ value)
{
    const int b = blockIdx.x;
    const int t = threadIdx.x;
    const int rowBase = b * 256;
    float a0 = 0.f, a1 = 0.f, a2 = 0.f, a3 = 0.f;
    for (int r = 0; r < 256; r++) {
        const int row = rowBase + r;
        const float w = g_weights[row];
        const float* vr = value + (size_t)row * FF;
        a0 += w * vr[t];
        a1 += w * vr[t + 256];
        a2 += w * vr[t + 512];
        a3 += w * vr[t + 768];
    }
    g_ctxpart[b * FF + t]       = a0;
    g_ctxpart[b * FF + t + 256] = a1;
    g_ctxpart[b * FF + t + 512] = a2;
    g_ctxpart[b * FF + t + 768] = a3;
}

__global__ __launch_bounds__(1024) void ctx_reduce(float* __restrict__ out)
{
    const int c = threadIdx.x;
    float s = 0.0f;
    for (int b = 0; b < 256; b++) s += g_ctxpart[b * FF + c];
    out[c] = s;
}

// ---------------------------------------------------------------------------
// Launch (serial splits; fused z=2 encoder GEMM — R8 structure)
// ---------------------------------------------------------------------------
extern "C" void kernel_launch(void* const* d_in, const int* in_sizes, int n_in,
                              void* d_out, int out_size)
{
    const float* key   = (const float*)d_in[0];
    const float* query = (const float*)d_in[1];
    const float* value = (const float*)d_in[2];
    const float* W0    = (const float*)d_in[3];
    const float* b0    = (const float*)d_in[4];
    const float* W1    = (const float*)d_in[5];
    const float* b1    = (const float*)d_in[6];
    const float* Wa    = (const float*)d_in[7];
    const float* ba    = (const float*)d_in[8];
    float* out = (float*)d_out;

    __half *in0h, *in0l, *in1h, *in1l;
    __half *w0h, *w0l, *w1h, *w1l, *wah, *wal;
    __half *qench, *qencl;
    cudaGetSymbolAddress((void**)&in0h, g_in0h);
    cudaGetSymbolAddress((void**)&in0l, g_in0l);
    cudaGetSymbolAddress((void**)&in1h, g_in1h);
    cudaGetSymbolAddress((void**)&in1l, g_in1l);
    cudaGetSymbolAddress((void**)&w0h, g_w0h);
    cudaGetSymbolAddress((void**)&w0l, g_w0l);
    cudaGetSymbolAddress((void**)&w1h, g_w1h);
    cudaGetSymbolAddress((void**)&w1l, g_w1l);
    cudaGetSymbolAddress((void**)&wah, g_wah);
    cudaGetSymbolAddress((void**)&wal, g_wal);
    cudaGetSymbolAddress((void**)&qench, g_qench);
    cudaGetSymbolAddress((void**)&qencl, g_qencl);

    cudaFuncSetAttribute(gemm_enc2, cudaFuncAttributeMaxDynamicSharedMemorySize, DYN_SMEM);
    cudaFuncSetAttribute(gemm_energy, cudaFuncAttributeMaxDynamicSharedMemorySize, DYN_SMEM);

    const int n4_in = NN * FF / 4;   // 16M float4
    const int n4_w  = FF * FF / 4;   // 256K float4
    split_kernel<<<n4_in / 1024, 256>>>((const float4*)query, (uint4*)in0h, (uint4*)in0l, n4_in);
    split_kernel<<<n4_in / 1024, 256>>>((const float4*)key,   (uint4*)in1h, (uint4*)in1l, n4_in);
    split_kernel<<<n4_w / 1024, 256>>>((const float4*)W0, (uint4*)w0h, (uint4*)w0l, n4_w);
    split_kernel<<<n4_w / 1024, 256>>>((const float4*)W1, (uint4*)w1h, (uint4*)w1l, n4_w);
    split_kernel<<<n4_w / 1024, 256>>>((const float4*)Wa, (uint4*)wah, (uint4*)wal, n4_w);

    dim3 grid2(FF / BN, NN / BM, 2);   // (8, 512, 2)
    gemm_enc2<<<grid2, NTHREADS, DYN_SMEM>>>(
        in0h, in0l, w0h, w0l, b0,
        in1h, in1l, w1h, w1l, b1, qench, qencl);

    dim3 grid(FF / BN, NN / BM);       // (8, 512)
    gemm_energy<<<grid, NTHREADS, DYN_SMEM>>>(qench, qencl, wah, wal, ba);
    softmax_k<<<1, 1024>>>();
    ctx_partial<<<256, 256>>>(value);
    ctx_reduce<<<1, 1024>>>(out);
}

// round 11
// speedup vs baseline: 1.0708x; 1.0708x over previous
#include <cuda_runtime.h>
#include <cuda_fp16.h>
#include <math.h>
#include <stdint.h>

#define NN 65536
#define FF 1024
#define BK 64
#define NCHUNK (FF / BK)     // 16
#define BM 256               // CTA rows
#define BN 128               // CTA cols

// per-stage smem: A hi/lo (256x64 halfs = 32KB each), B hi/lo (128x64 = 16KB each)
#define OFF_AH 0
#define OFF_AL 32768
#define OFF_BH 65536
#define OFF_BL 81920
#define STAGE_BYTES 98304
#define DYN_SMEM (2 * STAGE_BYTES)   // 192 KB, 2-stage

// ---------------------------------------------------------------------------
// Device scratch
// ---------------------------------------------------------------------------
__device__ __half g_in0h[(size_t)NN * FF], g_in0l[(size_t)NN * FF]; // query split
__device__ __half g_in1h[(size_t)NN * FF], g_in1l[(size_t)NN * FF]; // key split
__device__ __half g_w0h[FF * FF], g_w0l[FF * FF];
__device__ __half g_w1h[FF * FF], g_w1l[FF * FF];
__device__ __half g_wah[FF * FF], g_wal[FF * FF];
__device__ float  g_kenc[(size_t)NN * FF];                      // fp32 k_enc
__device__ __half g_qench[(size_t)NN * FF], g_qencl[(size_t)NN * FF];
__device__ float  g_epart[8 * NN];
__device__ float  g_energy[NN], g_weights[NN];
__device__ float  g_invZ[1];
__device__ float  g_ctxpart[256 * FF];

// ---------------------------------------------------------------------------
// PTX helpers (sm_80-class, arch-generic)
// ---------------------------------------------------------------------------
__device__ __forceinline__ uint32_t smem_u32(const void* p) {
    uint32_t a;
    asm("{ .reg .u64 t; cvta.to.shared.u64 t, %1; cvt.u32.u64 %0, t; }"
        : "=r"(a) : "l"(p));
    return a;
}

#define CP_ASYNC16(saddr, gptr) \
    asm volatile("cp.async.cg.shared.global [%0], [%1], 16;" \
                 :: "r"(saddr), "l"(gptr))
#define CP_COMMIT() asm volatile("cp.async.commit_group;" ::: "memory")
#define CP_WAIT0()  asm volatile("cp.async.wait_group 0;" ::: "memory")
#define CP_WAIT1()  asm volatile("cp.async.wait_group 1;" ::: "memory")

__device__ __forceinline__ void ldsm4(uint32_t* r, uint32_t a) {
    asm volatile("ldmatrix.sync.aligned.m8n8.x4.shared.b16 {%0,%1,%2,%3}, [%4];"
                 : "=r"(r[0]), "=r"(r[1]), "=r"(r[2]), "=r"(r[3]) : "r"(a));
}

__device__ __forceinline__ void mma16816(float* d, const uint32_t* a,
                                         uint32_t b0, uint32_t b1) {
    asm volatile(
        "mma.sync.aligned.m16n8k16.row.col.f32.f16.f16.f32 "
        "{%0,%1,%2,%3}, {%4,%5,%6,%7}, {%8,%9}, {%0,%1,%2,%3};"
        : "+f"(d[0]), "+f"(d[1]), "+f"(d[2]), "+f"(d[3])
        : "r"(a[0]), "r"(a[1]), "r"(a[2]), "r"(a[3]), "r"(b0), "r"(b1));
}

// 128B rows (8 chunks of 16B): chunk' = c ^ (r&7); conflict-free ldmatrix.
__device__ __forceinline__ uint32_t swz(int r, int c) {
    return (uint32_t)(r * 128 + ((c ^ (r & 7)) << 4));
}

__device__ __forceinline__ uint32_t pack_hi2(float a, float b) {
    __half2 h = __halves2half2(__float2half_rn(a), __float2half_rn(b));
    return *(uint32_t*)&h;
}
__device__ __forceinline__ uint32_t pack_lo2(float a, float b) {
    __half ha = __float2half_rn(a), hb = __float2half_rn(b);
    __half2 l = __halves2half2(__float2half_rn(a - __half2float(ha)),
                               __float2half_rn(b - __half2float(hb)));
    return *(uint32_t*)&l;
}

// ---------------------------------------------------------------------------
// Batched split fp32 -> (hi, lo) fp16: grid.y selects tensor.
// ---------------------------------------------------------------------------
__global__ __launch_bounds__(256) void split_batch(
    const float4* __restrict__ x0, uint4* __restrict__ h0, uint4* __restrict__ l0_,
    const float4* __restrict__ x1, uint4* __restrict__ h1, uint4* __restrict__ l1_,
    const float4* __restrict__ x2, uint4* __restrict__ h2, uint4* __restrict__ l2_)
{
    const float4* x = (blockIdx.y == 0) ? x0 : (blockIdx.y == 1) ? x1 : x2;
    uint4* hi = (blockIdx.y == 0) ? h0 : (blockIdx.y == 1) ? h1 : h2;
    uint4* lo = (blockIdx.y == 0) ? l0_ : (blockIdx.y == 1) ? l1_ : l2_;

    const int i0 = (blockIdx.x * 256 + threadIdx.x) * 4;
    float4 v0 = x[i0], v1 = x[i0 + 1], v2 = x[i0 + 2], v3 = x[i0 + 3];

    uint4 ho0, ho1, lo0, lo1;
    ho0.x = pack_hi2(v0.x, v0.y); ho0.y = pack_hi2(v0.z, v0.w);
    ho0.z = pack_hi2(v1.x, v1.y); ho0.w = pack_hi2(v1.z, v1.w);
    ho1.x = pack_hi2(v2.x, v2.y); ho1.y = pack_hi2(v2.z, v2.w);
    ho1.z = pack_hi2(v3.x, v3.y); ho1.w = pack_hi2(v3.z, v3.w);
    lo0.x = pack_lo2(v0.x, v0.y); lo0.y = pack_lo2(v0.z, v0.w);
    lo0.z = pack_lo2(v1.x, v1.y); lo0.w = pack_lo2(v1.z, v1.w);
    lo1.x = pack_lo2(v2.x, v2.y); lo1.y = pack_lo2(v2.z, v2.w);
    lo1.z = pack_lo2(v3.x, v3.y); lo1.w = pack_lo2(v3.z, v3.w);

    hi[i0 >> 1] = ho0; hi[(i0 >> 1) + 1] = ho1;
    lo[i0 >> 1] = lo0; lo[(i0 >> 1) + 1] = lo1;
}

// ---------------------------------------------------------------------------
// Mainloop: acc(256x128 fp32 fragments, warp tile 64x64) += A @ B^T, fp16x3.
// BK=64, 2-stage cp.async pipeline. (R8 exact)
// ---------------------------------------------------------------------------
__device__ __forceinline__ void mma_mainloop(
    const __half* __restrict__ Ah, const __half* __restrict__ Al,
    const __half* __restrict__ Bh, const __half* __restrict__ Bl,
    char* dsm, int rowBase, int colBase, int tid, float acc[4][8][4])
{
    const int lane = tid & 31;
    const int w = tid >> 5, wm = w >> 1, wn = w & 1;
    const uint32_t sbase = smem_u32(dsm);

#pragma unroll
    for (int mt = 0; mt < 4; mt++)
#pragma unroll
        for (int nt = 0; nt < 8; nt++)
#pragma unroll
            for (int q = 0; q < 4; q++) acc[mt][nt][q] = 0.0f;

    const int a_r0 = wm * 64 + (lane & 15);
    const int a_ch = lane >> 4;
    const int b_r0 = wn * 64 + (lane & 7) + ((lane & 16) >> 1);
    const int b_ch = (lane >> 3) & 1;

    auto load_stage = [&](int c, int slot) {
        const int k0 = c * BK;
        const uint32_t sb = sbase + slot * STAGE_BYTES;
#pragma unroll
        for (int i = 0; i < 8; i++) {               // A: 256 rows x 8 ck
            const int id = tid + i * 256;
            const int r = id >> 3, ck = id & 7;
            const uint32_t so = swz(r, ck);
            const size_t ga = (size_t)(rowBase + r) * FF + k0 + ck * 8;
            CP_ASYNC16(sb + OFF_AH + so, Ah + ga);
            CP_ASYNC16(sb + OFF_AL + so, Al + ga);
        }
#pragma unroll
        for (int i = 0; i < 4; i++) {               // B: 128 rows x 8 ck
            const int id = tid + i * 256;
            const int r = id >> 3, ck = id & 7;
            const uint32_t so = swz(r, ck);
            const size_t gb = (size_t)(colBase + r) * FF + k0 + ck * 8;
            CP_ASYNC16(sb + OFF_BH + so, Bh + gb);
            CP_ASYNC16(sb + OFF_BL + so, Bl + gb);
        }
    };

    load_stage(0, 0); CP_COMMIT();

    int s = 0;
    for (int c = 0; c < NCHUNK; c++) {
        if (c + 1 < NCHUNK) {
            load_stage(c + 1, s ^ 1);
            CP_COMMIT();
            CP_WAIT1();          // stage c complete
        } else {
            CP_WAIT0();
        }
        __syncthreads();         // stage c visible to all warps

        const uint32_t sb = sbase + s * STAGE_BYTES;
#pragma unroll
        for (int kk = 0; kk < 4; kk++) {
            uint32_t ah[4][4], al[4][4], bh[4][4], bl[4][4];
#pragma unroll
            for (int mt = 0; mt < 4; mt++) {
                const uint32_t so = swz(a_r0 + mt * 16, kk * 2 + a_ch);
                ldsm4(ah[mt], sb + OFF_AH + so);
                ldsm4(al[mt], sb + OFF_AL + so);
            }
#pragma unroll
            for (int p = 0; p < 4; p++) {
                const uint32_t so = swz(b_r0 + p * 16, kk * 2 + b_ch);
                ldsm4(bh[p], sb + OFF_BH + so);
                ldsm4(bl[p], sb + OFF_BL + so);
            }
#pragma unroll
            for (int mt = 0; mt < 4; mt++)
#pragma unroll
                for (int nt = 0; nt < 8; nt++) {
                    const int p = nt >> 1, o = (nt & 1) * 2;
                    mma16816(acc[mt][nt], ah[mt], bh[p][o], bh[p][o + 1]);
                    mma16816(acc[mt][nt], ah[mt], bl[p][o], bl[p][o + 1]);
                    mma16816(acc[mt][nt], al[mt], bh[p][o], bh[p][o + 1]);
                }
        }
        __syncthreads();         // all warps done reading stage s before reuse
        s ^= 1;
    }
}

// ---------------------------------------------------------------------------
// Fused GEMM1+GEMM2 (blockIdx.z): z=0 -> kenc fp32; z=1 -> qenc split hi/lo
// ---------------------------------------------------------------------------
__global__ __launch_bounds__(256, 1) void gemm_enc2(
    const __half* __restrict__ A0h, const __half* __restrict__ A0l,
    const __half* __restrict__ B0h, const __half* __restrict__ B0l,
    const float* __restrict__ bias0,
    const __half* __restrict__ A1h, const __half* __restrict__ A1l,
    const __half* __restrict__ B1h, const __half* __restrict__ B1l,
    const float* __restrict__ bias1,
    __half* __restrict__ O1h, __half* __restrict__ O1l)
{
    extern __shared__ __align__(1024) char dsm[];
    const int tid = threadIdx.x;
    const int rowBase = blockIdx.y * BM;
    const int colBase = blockIdx.x * BN;
    const int z = blockIdx.z;

    const __half* Ah = z ? A1h : A0h;
    const __half* Al = z ? A1l : A0l;
    const __half* Bh = z ? B1h : B0h;
    const __half* Bl = z ? B1l : B0l;
    const float* bias = z ? bias1 : bias0;

    float acc[4][8][4];
    mma_mainloop(Ah, Al, Bh, Bl, dsm, rowBase, colBase, tid, acc);

    const int lane = tid & 31;
    const int w = tid >> 5, wm = w >> 1, wn = w & 1;

#pragma unroll
    for (int nt = 0; nt < 8; nt++) {
        const int col0 = colBase + wn * 64 + nt * 8 + 2 * (lane & 3);
        const float2 bb = *(const float2*)&bias[col0];
#pragma unroll
        for (int mt = 0; mt < 4; mt++) {
            const int row0 = rowBase + wm * 64 + mt * 16 + (lane >> 2);
#pragma unroll
            for (int h = 0; h < 2; h++) {
                const int row = row0 + h * 8;
                const float v0 = fmaxf(acc[mt][nt][2 * h]     + bb.x, 0.0f);
                const float v1 = fmaxf(acc[mt][nt][2 * h + 1] + bb.y, 0.0f);
                if (z == 0) {
                    *(float2*)&g_kenc[(size_t)row * FF + col0] = make_float2(v0, v1);
                } else {
                    __half h0 = __float2half_rn(v0), h1 = __float2half_rn(v1);
                    __half l0 = __float2half_rn(v0 - __half2float(h0));
                    __half l1 = __float2half_rn(v1 - __half2float(h1));
                    *(__half2*)&O1h[(size_t)row * FF + col0] = __halves2half2(h0, h1);
                    *(__half2*)&O1l[(size_t)row * FF + col0] = __halves2half2(l0, l1);
                }
            }
        }
    }
}

// ---------------------------------------------------------------------------
// GEMM3: attn = qenc @ Wa^T + ba, fused energy-partial epilogue
// ---------------------------------------------------------------------------
__global__ __launch_bounds__(256, 1) void gemm_energy(
    const __half* __restrict__ Ah, const __half* __restrict__ Al,
    const __half* __restrict__ Bh, const __half* __restrict__ Bl,
    const float* __restrict__ ba)
{
    extern __shared__ __align__(1024) char dsm[];
    const int tid = threadIdx.x;
    const int rowBase = blockIdx.y * BM;
    const int colBase = blockIdx.x * BN;

    float acc[4][8][4];
    mma_mainloop(Ah, Al, Bh, Bl, dsm, rowBase, colBase, tid, acc);

    const int lane = tid & 31;
    const int w = tid >> 5, wm = w >> 1, wn = w & 1;

    float er[4][2];
#pragma unroll
    for (int mt = 0; mt < 4; mt++) { er[mt][0] = 0.0f; er[mt][1] = 0.0f; }

#pragma unroll
    for (int nt = 0; nt < 8; nt++) {
        const int col0 = colBase + wn * 64 + nt * 8 + 2 * (lane & 3);
        const float2 bb = *(const float2*)&ba[col0];
#pragma unroll
        for (int mt = 0; mt < 4; mt++) {
            const int row0 = rowBase + wm * 64 + mt * 16 + (lane >> 2);
#pragma unroll
            for (int h = 0; h < 2; h++) {
                const int row = row0 + h * 8;
                const float2 kk2 = *(const float2*)&g_kenc[(size_t)row * FF + col0];
                const float v0 = acc[mt][nt][2 * h]     + bb.x;
                const float v1 = acc[mt][nt][2 * h + 1] + bb.y;
                er[mt][h] += v0 * kk2.x + v1 * kk2.y;
            }
        }
    }

#pragma unroll
    for (int mt = 0; mt < 4; mt++) {
#pragma unroll
        for (int h = 0; h < 2; h++) {
            er[mt][h] += __shfl_xor_sync(0xffffffffu, er[mt][h], 1);
            er[mt][h] += __shfl_xor_sync(0xffffffffu, er[mt][h], 2);
        }
    }

    float* e_sm = (float*)dsm;   // [2 wn][256 rows]
    __syncthreads();
    if ((lane & 3) == 0) {
        const int rl0 = wm * 64 + (lane >> 2);
#pragma unroll
        for (int mt = 0; mt < 4; mt++) {
            e_sm[wn * 256 + rl0 + mt * 16]     = er[mt][0];
            e_sm[wn * 256 + rl0 + mt * 16 + 8] = er[mt][1];
        }
    }
    __syncthreads();
    if (tid < 256) {
        float e = e_sm[tid] + e_sm[256 + tid];
        g_epart[blockIdx.x * NN + rowBase + tid] = e;
    }
}

// ---------------------------------------------------------------------------
// Softmax: partial-reduce fused; weights left UNNORMALIZED, 1/Z published.
// ---------------------------------------------------------------------------
__global__ __launch_bounds__(1024) void softmax_k()
{
    __shared__ float red[1024];
    const int t = threadIdx.x;

    float m = -1e30f;
    for (int i = t; i < NN; i += 1024) {
        float e = 0.0f;
#pragma unroll
        for (int p = 0; p < 8; p++) e += g_epart[p * NN + i];
        g_energy[i] = e;
        m = fmaxf(m, e);
    }
    red[t] = m;
    __syncthreads();
    for (int s = 512; s > 0; s >>= 1) {
        if (t < s) red[t] = fmaxf(red[t], red[t + s]);
        __syncthreads();
    }
    const float mx = red[0];
    __syncthreads();

    float sum = 0.0f;
    for (int i = t; i < NN; i += 1024) {
        const float w = expf(g_energy[i] - mx);
        g_weights[i] = w;
        sum += w;
    }
    red[t] = sum;
    __syncthreads();
    for (int s = 512; s > 0; s >>= 1) {
        if (t < s) red[t] += red[t + s];
        __syncthreads();
    }
    if (t == 0) g_invZ[0] = 1.0f / red[0];
}

__global__ __launch_bounds__(256) void ctx_partial(const float* __restrict__ value)
{
    const int b = blockIdx.x;
    const int t = threadIdx.x;
    const int rowBase = b * 256;
    float a0 = 0.f, a1 = 0.f, a2 = 0.f, a3 = 0.f;
    for (int r = 0; r < 256; r++) {
        const int row = rowBase + r;
        const float w = g_weights[row];
        const float* vr = value + (size_t)row * FF;
        a0 += w * vr[t];
        a1 += w * vr[t + 256];
        a2 += w * vr[t + 512];
        a3 += w * vr[t + 768];
    }
    g_ctxpart[b * FF + t]       = a0;
    g_ctxpart[b * FF + t + 256] = a1;
    g_ctxpart[b * FF + t + 512] = a2;
    g_ctxpart[b * FF + t + 768] = a3;
}

__global__ __launch_bounds__(1024) void ctx_reduce(float* __restrict__ out)
{
    const int c = threadIdx.x;
    const float invZ = g_invZ[0];
    float s = 0.0f;
    for (int b = 0; b < 256; b++) s += g_ctxpart[b * FF + c];
    out[c] = s * invZ;
}

// ---------------------------------------------------------------------------
// Launch
// ---------------------------------------------------------------------------
extern "C" void kernel_launch(void* const* d_in, const int* in_sizes, int n_in,
                              void* d_out, int out_size)
{
    const float* key   = (const float*)d_in[0];
    const float* query = (const float*)d_in[1];
    const float* value = (const float*)d_in[2];
    const float* W0    = (const float*)d_in[3];
    const float* b0    = (const float*)d_in[4];
    const float* W1    = (const float*)d_in[5];
    const float* b1    = (const float*)d_in[6];
    const float* Wa    = (const float*)d_in[7];
    const float* ba    = (const float*)d_in[8];
    float* out = (float*)d_out;

    __half *in0h, *in0l, *in1h, *in1l;
    __half *w0h, *w0l, *w1h, *w1l, *wah, *wal;
    __half *qench, *qencl;
    cudaGetSymbolAddress((void**)&in0h, g_in0h);
    cudaGetSymbolAddress((void**)&in0l, g_in0l);
    cudaGetSymbolAddress((void**)&in1h, g_in1h);
    cudaGetSymbolAddress((void**)&in1l, g_in1l);
    cudaGetSymbolAddress((void**)&w0h, g_w0h);
    cudaGetSymbolAddress((void**)&w0l, g_w0l);
    cudaGetSymbolAddress((void**)&w1h, g_w1h);
    cudaGetSymbolAddress((void**)&w1l, g_w1l);
    cudaGetSymbolAddress((void**)&wah, g_wah);
    cudaGetSymbolAddress((void**)&wal, g_wal);
    cudaGetSymbolAddress((void**)&qench, g_qench);
    cudaGetSymbolAddress((void**)&qencl, g_qencl);

    cudaFuncSetAttribute(gemm_enc2, cudaFuncAttributeMaxDynamicSharedMemorySize, DYN_SMEM);
    cudaFuncSetAttribute(gemm_energy, cudaFuncAttributeMaxDynamicSharedMemorySize, DYN_SMEM);

    const int n4_in = NN * FF / 4;   // 16M float4
    const int n4_w  = FF * FF / 4;   // 256K float4

    // inputs: query (y=0), key (y=1) in one launch
    {
        dim3 g(n4_in / 1024, 2);
        split_batch<<<g, 256>>>(
            (const float4*)query, (uint4*)in0h, (uint4*)in0l,
            (const float4*)key,   (uint4*)in1h, (uint4*)in1l,
            (const float4*)key,   (uint4*)in1h, (uint4*)in1l);  // y=2 unused
    }
    // weights: W0 (y=0), W1 (y=1), Wa (y=2) in one launch
    {
        dim3 g(n4_w / 1024, 3);
        split_batch<<<g, 256>>>(
            (const float4*)W0, (uint4*)w0h, (uint4*)w0l,
            (const float4*)W1, (uint4*)w1h, (uint4*)w1l,
            (const float4*)Wa, (uint4*)wah, (uint4*)wal);
    }

    dim3 grid2(FF / BN, NN / BM, 2);   // (8, 256, 2)
    gemm_enc2<<<grid2, 256, DYN_SMEM>>>(
        in0h, in0l, w0h, w0l, b0,
        in1h, in1l, w1h, w1l, b1, qench, qencl);

    dim3 grid(FF / BN, NN / BM);       // (8, 256)
    gemm_energy<<<grid, 256, DYN_SMEM>>>(qench, qencl, wah, wal, ba);
    softmax_k<<<1, 1024>>>();
    ctx_partial<<<256, 256>>>(value);
    ctx_reduce<<<1, 1024>>>(out);
}

// round 12
// speedup vs baseline: 1.0948x; 1.0224x over previous
#include <cuda_runtime.h>
#include <cuda_fp16.h>
#include <math.h>
#include <stdint.h>

#define NN 65536
#define FF 1024
#define BK 64
#define NCHUNK (FF / BK)     // 16
#define BM 256               // CTA rows
#define BN 128               // CTA cols

// per-stage smem: A hi/lo (256x64 halfs = 32KB each), B hi/lo (128x64 = 16KB each)
#define OFF_AH 0
#define OFF_AL 32768
#define OFF_BH 65536
#define OFF_BL 81920
#define STAGE_BYTES 98304
#define DYN_SMEM (2 * STAGE_BYTES)   // 192 KB, 2-stage

// ---------------------------------------------------------------------------
// Device scratch
// ---------------------------------------------------------------------------
__device__ __half g_in0h[(size_t)NN * FF], g_in0l[(size_t)NN * FF]; // query split
__device__ __half g_in1h[(size_t)NN * FF], g_in1l[(size_t)NN * FF]; // key split
__device__ __half g_w0h[FF * FF], g_w0l[FF * FF];
__device__ __half g_w1h[FF * FF], g_w1l[FF * FF];
__device__ __half g_wah[FF * FF], g_wal[FF * FF];
__device__ float  g_kenc[(size_t)NN * FF];                      // fp32 k_enc
__device__ __half g_qench[(size_t)NN * FF], g_qencl[(size_t)NN * FF];
__device__ float  g_epart[8 * NN];
__device__ float  g_energy[NN], g_weights[NN];
__device__ float  g_invZ[1];
__device__ float  g_ctxpart[256 * FF];

// ---------------------------------------------------------------------------
// PTX helpers (sm_80-class, arch-generic)
// ---------------------------------------------------------------------------
__device__ __forceinline__ uint32_t smem_u32(const void* p) {
    uint32_t a;
    asm("{ .reg .u64 t; cvta.to.shared.u64 t, %1; cvt.u32.u64 %0, t; }"
        : "=r"(a) : "l"(p));
    return a;
}

#define CP_ASYNC16(saddr, gptr) \
    asm volatile("cp.async.cg.shared.global [%0], [%1], 16;" \
                 :: "r"(saddr), "l"(gptr))
#define CP_COMMIT() asm volatile("cp.async.commit_group;" ::: "memory")
#define CP_WAIT0()  asm volatile("cp.async.wait_group 0;" ::: "memory")
#define CP_WAIT1()  asm volatile("cp.async.wait_group 1;" ::: "memory")

__device__ __forceinline__ void ldsm4(uint32_t* r, uint32_t a) {
    asm volatile("ldmatrix.sync.aligned.m8n8.x4.shared.b16 {%0,%1,%2,%3}, [%4];"
                 : "=r"(r[0]), "=r"(r[1]), "=r"(r[2]), "=r"(r[3]) : "r"(a));
}

__device__ __forceinline__ void mma16816(float* d, const uint32_t* a,
                                         uint32_t b0, uint32_t b1) {
    asm volatile(
        "mma.sync.aligned.m16n8k16.row.col.f32.f16.f16.f32 "
        "{%0,%1,%2,%3}, {%4,%5,%6,%7}, {%8,%9}, {%0,%1,%2,%3};"
        : "+f"(d[0]), "+f"(d[1]), "+f"(d[2]), "+f"(d[3])
        : "r"(a[0]), "r"(a[1]), "r"(a[2]), "r"(a[3]), "r"(b0), "r"(b1));
}

// 128B rows (8 chunks of 16B): chunk' = c ^ (r&7); conflict-free ldmatrix.
__device__ __forceinline__ uint32_t swz(int r, int c) {
    return (uint32_t)(r * 128 + ((c ^ (r & 7)) << 4));
}

__device__ __forceinline__ uint32_t pack_hi2(float a, float b) {
    __half2 h = __halves2half2(__float2half_rn(a), __float2half_rn(b));
    return *(uint32_t*)&h;
}
__device__ __forceinline__ uint32_t pack_lo2(float a, float b) {
    __half ha = __float2half_rn(a), hb = __float2half_rn(b);
    __half2 l = __halves2half2(__float2half_rn(a - __half2float(ha)),
                               __float2half_rn(b - __half2float(hb)));
    return *(uint32_t*)&l;
}

// ---------------------------------------------------------------------------
// Batched split fp32 -> (hi, lo) fp16: grid.y selects tensor.
// Pair-stride mapping: thread t handles float4 pair (2k, 2k+1), k=blk*256+t,
// 4 pairs per thread at stride 256 -> coalesced 32B/thread reads, contiguous
// uint4 writes across the warp.
// ---------------------------------------------------------------------------
__global__ __launch_bounds__(256) void split_batch(
    const float4* __restrict__ x0, uint4* __restrict__ h0, uint4* __restrict__ l0_,
    const float4* __restrict__ x1, uint4* __restrict__ h1, uint4* __restrict__ l1_,
    const float4* __restrict__ x2, uint4* __restrict__ h2, uint4* __restrict__ l2_)
{
    const float4* x = (blockIdx.y == 0) ? x0 : (blockIdx.y == 1) ? x1 : x2;
    uint4* hi = (blockIdx.y == 0) ? h0 : (blockIdx.y == 1) ? h1 : h2;
    uint4* lo = (blockIdx.y == 0) ? l0_ : (blockIdx.y == 1) ? l1_ : l2_;

    const int kbase = blockIdx.x * 1024 + threadIdx.x;   // uint4 index base
#pragma unroll
    for (int j = 0; j < 4; j++) {
        const int k = kbase + j * 256;
        const float4 v0 = x[2 * k], v1 = x[2 * k + 1];
        uint4 hh, ll;
        hh.x = pack_hi2(v0.x, v0.y); hh.y = pack_hi2(v0.z, v0.w);
        hh.z = pack_hi2(v1.x, v1.y); hh.w = pack_hi2(v1.z, v1.w);
        ll.x = pack_lo2(v0.x, v0.y); ll.y = pack_lo2(v0.z, v0.w);
        ll.z = pack_lo2(v1.x, v1.y); ll.w = pack_lo2(v1.z, v1.w);
        hi[k] = hh;
        lo[k] = ll;
    }
}

// ---------------------------------------------------------------------------
// Mainloop: acc(256x128 fp32 fragments, warp tile 64x64) += A @ B^T, fp16x3.
// BK=64, 2-stage cp.async pipeline. A-fragments streamed per-mt to keep the
// live register set under the 255 cap (no spills).
// ---------------------------------------------------------------------------
__device__ __forceinline__ void mma_mainloop(
    const __half* __restrict__ Ah, const __half* __restrict__ Al,
    const __half* __restrict__ Bh, const __half* __restrict__ Bl,
    char* dsm, int rowBase, int colBase, int tid, float acc[4][8][4])
{
    const int lane = tid & 31;
    const int w = tid >> 5, wm = w >> 1, wn = w & 1;
    const uint32_t sbase = smem_u32(dsm);

#pragma unroll
    for (int mt = 0; mt < 4; mt++)
#pragma unroll
        for (int nt = 0; nt < 8; nt++)
#pragma unroll
            for (int q = 0; q < 4; q++) acc[mt][nt][q] = 0.0f;

    const int a_r0 = wm * 64 + (lane & 15);
    const int a_ch = lane >> 4;
    const int b_r0 = wn * 64 + (lane & 7) + ((lane & 16) >> 1);
    const int b_ch = (lane >> 3) & 1;

    auto load_stage = [&](int c, int slot) {
        const int k0 = c * BK;
        const uint32_t sb = sbase + slot * STAGE_BYTES;
#pragma unroll
        for (int i = 0; i < 8; i++) {               // A: 256 rows x 8 ck
            const int id = tid + i * 256;
            const int r = id >> 3, ck = id & 7;
            const uint32_t so = swz(r, ck);
            const size_t ga = (size_t)(rowBase + r) * FF + k0 + ck * 8;
            CP_ASYNC16(sb + OFF_AH + so, Ah + ga);
            CP_ASYNC16(sb + OFF_AL + so, Al + ga);
        }
#pragma unroll
        for (int i = 0; i < 4; i++) {               // B: 128 rows x 8 ck
            const int id = tid + i * 256;
            const int r = id >> 3, ck = id & 7;
            const uint32_t so = swz(r, ck);
            const size_t gb = (size_t)(colBase + r) * FF + k0 + ck * 8;
            CP_ASYNC16(sb + OFF_BH + so, Bh + gb);
            CP_ASYNC16(sb + OFF_BL + so, Bl + gb);
        }
    };

    load_stage(0, 0); CP_COMMIT();

    int s = 0;
    for (int c = 0; c < NCHUNK; c++) {
        if (c + 1 < NCHUNK) {
            load_stage(c + 1, s ^ 1);
            CP_COMMIT();
            CP_WAIT1();          // stage c complete
        } else {
            CP_WAIT0();
        }
        __syncthreads();         // stage c visible to all warps

        const uint32_t sb = sbase + s * STAGE_BYTES;
#pragma unroll
        for (int kk = 0; kk < 4; kk++) {
            // B fragments resident for the whole kk step (32 regs)
            uint32_t bh[4][4], bl[4][4];
#pragma unroll
            for (int p = 0; p < 4; p++) {
                const uint32_t so = swz(b_r0 + p * 16, kk * 2 + b_ch);
                ldsm4(bh[p], sb + OFF_BH + so);
                ldsm4(bl[p], sb + OFF_BL + so);
            }
            // A fragments streamed per-mt (8 regs live)
#pragma unroll
            for (int mt = 0; mt < 4; mt++) {
                uint32_t ah[4], al[4];
                const uint32_t so = swz(a_r0 + mt * 16, kk * 2 + a_ch);
                ldsm4(ah, sb + OFF_AH + so);
                ldsm4(al, sb + OFF_AL + so);
#pragma unroll
                for (int nt = 0; nt < 8; nt++) {
                    const int p = nt >> 1, o = (nt & 1) * 2;
                    mma16816(acc[mt][nt], ah, bh[p][o], bh[p][o + 1]);
                    mma16816(acc[mt][nt], ah, bl[p][o], bl[p][o + 1]);
                    mma16816(acc[mt][nt], al, bh[p][o], bh[p][o + 1]);
                }
            }
        }
        __syncthreads();         // all warps done reading stage s before reuse
        s ^= 1;
    }
}

// ---------------------------------------------------------------------------
// Fused GEMM1+GEMM2 (blockIdx.z): z=0 -> kenc fp32; z=1 -> qenc split hi/lo
// ---------------------------------------------------------------------------
__global__ __launch_bounds__(256, 1) void gemm_enc2(
    const __half* __restrict__ A0h, const __half* __restrict__ A0l,
    const __half* __restrict__ B0h, const __half* __restrict__ B0l,
    const float* __restrict__ bias0,
    const __half* __restrict__ A1h, const __half* __restrict__ A1l,
    const __half* __restrict__ B1h, const __half* __restrict__ B1l,
    const float* __restrict__ bias1,
    __half* __restrict__ O1h, __half* __restrict__ O1l)
{
    extern __shared__ __align__(1024) char dsm[];
    const int tid = threadIdx.x;
    const int rowBase = blockIdx.y * BM;
    const int colBase = blockIdx.x * BN;
    const int z = blockIdx.z;

    const __half* Ah = z ? A1h : A0h;
    const __half* Al = z ? A1l : A0l;
    const __half* Bh = z ? B1h : B0h;
    const __half* Bl = z ? B1l : B0l;
    const float* bias = z ? bias1 : bias0;

    float acc[4][8][4];
    mma_mainloop(Ah, Al, Bh, Bl, dsm, rowBase, colBase, tid, acc);

    const int lane = tid & 31;
    const int w = tid >> 5, wm = w >> 1, wn = w & 1;

#pragma unroll
    for (int nt = 0; nt < 8; nt++) {
        const int col0 = colBase + wn * 64 + nt * 8 + 2 * (lane & 3);
        const float2 bb = *(const float2*)&bias[col0];
#pragma unroll
        for (int mt = 0; mt < 4; mt++) {
            const int row0 = rowBase + wm * 64 + mt * 16 + (lane >> 2);
#pragma unroll
            for (int h = 0; h < 2; h++) {
                const int row = row0 + h * 8;
                const float v0 = fmaxf(acc[mt][nt][2 * h]     + bb.x, 0.0f);
                const float v1 = fmaxf(acc[mt][nt][2 * h + 1] + bb.y, 0.0f);
                if (z == 0) {
                    *(float2*)&g_kenc[(size_t)row * FF + col0] = make_float2(v0, v1);
                } else {
                    __half h0 = __float2half_rn(v0), h1 = __float2half_rn(v1);
                    __half l0 = __float2half_rn(v0 - __half2float(h0));
                    __half l1 = __float2half_rn(v1 - __half2float(h1));
                    *(__half2*)&O1h[(size_t)row * FF + col0] = __halves2half2(h0, h1);
                    *(__half2*)&O1l[(size_t)row * FF + col0] = __halves2half2(l0, l1);
                }
            }
        }
    }
}

// ---------------------------------------------------------------------------
// GEMM3: attn = qenc @ Wa^T + ba, fused energy-partial epilogue
// ---------------------------------------------------------------------------
__global__ __launch_bounds__(256, 1) void gemm_energy(
    const __half* __restrict__ Ah, const __half* __restrict__ Al,
    const __half* __restrict__ Bh, const __half* __restrict__ Bl,
    const float* __restrict__ ba)
{
    extern __shared__ __align__(1024) char dsm[];
    const int tid = threadIdx.x;
    const int rowBase = blockIdx.y * BM;
    const int colBase = blockIdx.x * BN;

    float acc[4][8][4];
    mma_mainloop(Ah, Al, Bh, Bl, dsm, rowBase, colBase, tid, acc);

    const int lane = tid & 31;
    const int w = tid >> 5, wm = w >> 1, wn = w & 1;

    float er[4][2];
#pragma unroll
    for (int mt = 0; mt < 4; mt++) { er[mt][0] = 0.0f; er[mt][1] = 0.0f; }

#pragma unroll
    for (int nt = 0; nt < 8; nt++) {
        const int col0 = colBase + wn * 64 + nt * 8 + 2 * (lane & 3);
        const float2 bb = *(const float2*)&ba[col0];
#pragma unroll
        for (int mt = 0; mt < 4; mt++) {
            const int row0 = rowBase + wm * 64 + mt * 16 + (lane >> 2);
#pragma unroll
            for (int h = 0; h < 2; h++) {
                const int row = row0 + h * 8;
                const float2 kk2 = *(const float2*)&g_kenc[(size_t)row * FF + col0];
                const float v0 = acc[mt][nt][2 * h]     + bb.x;
                const float v1 = acc[mt][nt][2 * h + 1] + bb.y;
                er[mt][h] += v0 * kk2.x + v1 * kk2.y;
            }
        }
    }

#pragma unroll
    for (int mt = 0; mt < 4; mt++) {
#pragma unroll
        for (int h = 0; h < 2; h++) {
            er[mt][h] += __shfl_xor_sync(0xffffffffu, er[mt][h], 1);
            er[mt][h] += __shfl_xor_sync(0xffffffffu, er[mt][h], 2);
        }
    }

    float* e_sm = (float*)dsm;   // [2 wn][256 rows]
    __syncthreads();
    if ((lane & 3) == 0) {
        const int rl0 = wm * 64 + (lane >> 2);
#pragma unroll
        for (int mt = 0; mt < 4; mt++) {
            e_sm[wn * 256 + rl0 + mt * 16]     = er[mt][0];
            e_sm[wn * 256 + rl0 + mt * 16 + 8] = er[mt][1];
        }
    }
    __syncthreads();
    if (tid < 256) {
        float e = e_sm[tid] + e_sm[256 + tid];
        g_epart[blockIdx.x * NN + rowBase + tid] = e;
    }
}

// ---------------------------------------------------------------------------
// Softmax: partial-reduce fused; weights left UNNORMALIZED, 1/Z published.
// ---------------------------------------------------------------------------
__global__ __launch_bounds__(1024) void softmax_k()
{
    __shared__ float red[1024];
    const int t = threadIdx.x;

    float m = -1e30f;
    for (int i = t; i < NN; i += 1024) {
        float e = 0.0f;
#pragma unroll
        for (int p = 0; p < 8; p++) e += g_epart[p * NN + i];
        g_energy[i] = e;
        m = fmaxf(m, e);
    }
    red[t] = m;
    __syncthreads();
    for (int s = 512; s > 0; s >>= 1) {
        if (t < s) red[t] = fmaxf(red[t], red[t + s]);
        __syncthreads();
    }
    const float mx = red[0];
    __syncthreads();

    float sum = 0.0f;
    for (int i = t; i < NN; i += 1024) {
        const float w = expf(g_energy[i] - mx);
        g_weights[i] = w;
        sum += w;
    }
    red[t] = sum;
    __syncthreads();
    for (int s = 512; s > 0; s >>= 1) {
        if (t < s) red[t] += red[t + s];
        __syncthreads();
    }
    if (t == 0) g_invZ[0] = 1.0f / red[0];
}

__global__ __launch_bounds__(256) void ctx_partial(const float* __restrict__ value)
{
    const int b = blockIdx.x;
    const int t = threadIdx.x;
    const int rowBase = b * 256;
    float a0 = 0.f, a1 = 0.f, a2 = 0.f, a3 = 0.f;
    for (int r = 0; r < 256; r++) {
        const int row = rowBase + r;
        const float w = g_weights[row];
        const float* vr = value + (size_t)row * FF;
        a0 += w * vr[t];
        a1 += w * vr[t + 256];
        a2 += w * vr[t + 512];
        a3 += w * vr[t + 768];
    }
    g_ctxpart[b * FF + t]       = a0;
    g_ctxpart[b * FF + t + 256] = a1;
    g_ctxpart[b * FF + t + 512] = a2;
    g_ctxpart[b * FF + t + 768] = a3;
}

__global__ __launch_bounds__(1024) void ctx_reduce(float* __restrict__ out)
{
    const int c = threadIdx.x;
    const float invZ = g_invZ[0];
    float s = 0.0f;
    for (int b = 0; b < 256; b++) s += g_ctxpart[b * FF + c];
    out[c] = s * invZ;
}

// ---------------------------------------------------------------------------
// Launch
// ---------------------------------------------------------------------------
extern "C" void kernel_launch(void* const* d_in, const int* in_sizes, int n_in,
                              void* d_out, int out_size)
{
    const float* key   = (const float*)d_in[0];
    const float* query = (const float*)d_in[1];
    const float* value = (const float*)d_in[2];
    const float* W0    = (const float*)d_in[3];
    const float* b0    = (const float*)d_in[4];
    const float* W1    = (const float*)d_in[5];
    const float* b1    = (const float*)d_in[6];
    const float* Wa    = (const float*)d_in[7];
    const float* ba    = (const float*)d_in[8];
    float* out = (float*)d_out;

    __half *in0h, *in0l, *in1h, *in1l;
    __half *w0h, *w0l, *w1h, *w1l, *wah, *wal;
    __half *qench, *qencl;
    cudaGetSymbolAddress((void**)&in0h, g_in0h);
    cudaGetSymbolAddress((void**)&in0l, g_in0l);
    cudaGetSymbolAddress((void**)&in1h, g_in1h);
    cudaGetSymbolAddress((void**)&in1l, g_in1l);
    cudaGetSymbolAddress((void**)&w0h, g_w0h);
    cudaGetSymbolAddress((void**)&w0l, g_w0l);
    cudaGetSymbolAddress((void**)&w1h, g_w1h);
    cudaGetSymbolAddress((void**)&w1l, g_w1l);
    cudaGetSymbolAddress((void**)&wah, g_wah);
    cudaGetSymbolAddress((void**)&wal, g_wal);
    cudaGetSymbolAddress((void**)&qench, g_qench);
    cudaGetSymbolAddress((void**)&qencl, g_qencl);

    cudaFuncSetAttribute(gemm_enc2, cudaFuncAttributeMaxDynamicSharedMemorySize, DYN_SMEM);
    cudaFuncSetAttribute(gemm_energy, cudaFuncAttributeMaxDynamicSharedMemorySize, DYN_SMEM);

    const int n4_in = NN * FF / 4;   // 16M float4
    const int n4_w  = FF * FF / 4;   // 256K float4

    // inputs: query (y=0), key (y=1) in one launch
    {
        dim3 g(n4_in / 2048, 2);
        split_batch<<<g, 256>>>(
            (const float4*)query, (uint4*)in0h, (uint4*)in0l,
            (const float4*)key,   (uint4*)in1h, (uint4*)in1l,
            (const float4*)key,   (uint4*)in1h, (uint4*)in1l);  // y=2 unused
    }
    // weights: W0 (y=0), W1 (y=1), Wa (y=2) in one launch
    {
        dim3 g(n4_w / 2048, 3);
        split_batch<<<g, 256>>>(
            (const float4*)W0, (uint4*)w0h, (uint4*)w0l,
            (const float4*)W1, (uint4*)w1h, (uint4*)w1l,
            (const float4*)Wa, (uint4*)wah, (uint4*)wal);
    }

    dim3 grid2(FF / BN, NN / BM, 2);   // (8, 256, 2)
    gemm_enc2<<<grid2, 256, DYN_SMEM>>>(
        in0h, in0l, w0h, w0l, b0,
        in1h, in1l, w1h, w1l, b1, qench, qencl);

    dim3 grid(FF / BN, NN / BM);       // (8, 256)
    gemm_energy<<<grid, 256, DYN_SMEM>>>(qench, qencl, wah, wal, ba);
    softmax_k<<<1, 1024>>>();
    ctx_partial<<<256, 256>>>(value);
    ctx_reduce<<<1, 1024>>>(out);
}

// round 13
// speedup vs baseline: 1.1092x; 1.0132x over previous
#include <cuda_runtime.h>
#include <cuda_fp16.h>
#include <math.h>
#include <stdint.h>

#define NN 65536
#define FF 1024
#define BK 64
#define NCHUNK (FF / BK)     // 16
#define BM 256               // CTA rows
#define BN 128               // CTA cols

// per-stage smem: A hi/lo (256x64 halfs = 32KB each), B hi/lo (128x64 = 16KB each)
#define OFF_AH 0
#define OFF_AL 32768
#define OFF_BH 65536
#define OFF_BL 81920
#define STAGE_BYTES 98304
#define DYN_SMEM (2 * STAGE_BYTES)   // 192 KB, 2-stage

// ---------------------------------------------------------------------------
// Device scratch
// ---------------------------------------------------------------------------
__device__ __half g_in0h[(size_t)NN * FF], g_in0l[(size_t)NN * FF]; // query split
__device__ __half g_in1h[(size_t)NN * FF], g_in1l[(size_t)NN * FF]; // key split
__device__ __half g_w0h[FF * FF], g_w0l[FF * FF];
__device__ __half g_w1h[FF * FF], g_w1l[FF * FF];
__device__ __half g_wah[FF * FF], g_wal[FF * FF];
__device__ float  g_kenc[(size_t)NN * FF];                      // fp32 k_enc
__device__ __half g_qench[(size_t)NN * FF], g_qencl[(size_t)NN * FF];
__device__ float  g_epart[8 * NN];
__device__ float  g_energy[NN];
__device__ float  g_maxpart[64];
__device__ float  g_mx[1];
__device__ float  g_wsum[256];
__device__ float  g_ctxpart[256 * FF];

// ---------------------------------------------------------------------------
// PTX helpers (sm_80-class, arch-generic)
// ---------------------------------------------------------------------------
__device__ __forceinline__ uint32_t smem_u32(const void* p) {
    uint32_t a;
    asm("{ .reg .u64 t; cvta.to.shared.u64 t, %1; cvt.u32.u64 %0, t; }"
        : "=r"(a) : "l"(p));
    return a;
}

#define CP_ASYNC16(saddr, gptr) \
    asm volatile("cp.async.cg.shared.global [%0], [%1], 16;" \
                 :: "r"(saddr), "l"(gptr))
#define CP_COMMIT() asm volatile("cp.async.commit_group;" ::: "memory")
#define CP_WAIT0()  asm volatile("cp.async.wait_group 0;" ::: "memory")
#define CP_WAIT1()  asm volatile("cp.async.wait_group 1;" ::: "memory")

__device__ __forceinline__ void ldsm4(uint32_t* r, uint32_t a) {
    asm volatile("ldmatrix.sync.aligned.m8n8.x4.shared.b16 {%0,%1,%2,%3}, [%4];"
                 : "=r"(r[0]), "=r"(r[1]), "=r"(r[2]), "=r"(r[3]) : "r"(a));
}

__device__ __forceinline__ void mma16816(float* d, const uint32_t* a,
                                         uint32_t b0, uint32_t b1) {
    asm volatile(
        "mma.sync.aligned.m16n8k16.row.col.f32.f16.f16.f32 "
        "{%0,%1,%2,%3}, {%4,%5,%6,%7}, {%8,%9}, {%0,%1,%2,%3};"
        : "+f"(d[0]), "+f"(d[1]), "+f"(d[2]), "+f"(d[3])
        : "r"(a[0]), "r"(a[1]), "r"(a[2]), "r"(a[3]), "r"(b0), "r"(b1));
}

// 128B rows (8 chunks of 16B): chunk' = c ^ (r&7); conflict-free ldmatrix.
__device__ __forceinline__ uint32_t swz(int r, int c) {
    return (uint32_t)(r * 128 + ((c ^ (r & 7)) << 4));
}

__device__ __forceinline__ uint32_t pack_hi2(float a, float b) {
    __half2 h = __halves2half2(__float2half_rn(a), __float2half_rn(b));
    return *(uint32_t*)&h;
}
__device__ __forceinline__ uint32_t pack_lo2(float a, float b) {
    __half ha = __float2half_rn(a), hb = __float2half_rn(b);
    __half2 l = __halves2half2(__float2half_rn(a - __half2float(ha)),
                               __float2half_rn(b - __half2float(hb)));
    return *(uint32_t*)&l;
}

// ---------------------------------------------------------------------------
// Batched split fp32 -> (hi, lo) fp16: grid.y selects tensor.
// ---------------------------------------------------------------------------
__global__ __launch_bounds__(256) void split_batch(
    const float4* __restrict__ x0, uint4* __restrict__ h0, uint4* __restrict__ l0_,
    const float4* __restrict__ x1, uint4* __restrict__ h1, uint4* __restrict__ l1_,
    const float4* __restrict__ x2, uint4* __restrict__ h2, uint4* __restrict__ l2_)
{
    const float4* x = (blockIdx.y == 0) ? x0 : (blockIdx.y == 1) ? x1 : x2;
    uint4* hi = (blockIdx.y == 0) ? h0 : (blockIdx.y == 1) ? h1 : h2;
    uint4* lo = (blockIdx.y == 0) ? l0_ : (blockIdx.y == 1) ? l1_ : l2_;

    const int kbase = blockIdx.x * 1024 + threadIdx.x;   // uint4 index base
#pragma unroll
    for (int j = 0; j < 4; j++) {
        const int k = kbase + j * 256;
        const float4 v0 = x[2 * k], v1 = x[2 * k + 1];
        uint4 hh, ll;
        hh.x = pack_hi2(v0.x, v0.y); hh.y = pack_hi2(v0.z, v0.w);
        hh.z = pack_hi2(v1.x, v1.y); hh.w = pack_hi2(v1.z, v1.w);
        ll.x = pack_lo2(v0.x, v0.y); ll.y = pack_lo2(v0.z, v0.w);
        ll.z = pack_lo2(v1.x, v1.y); ll.w = pack_lo2(v1.z, v1.w);
        hi[k] = hh;
        lo[k] = ll;
    }
}

// ---------------------------------------------------------------------------
// Mainloop: acc(256x128 fp32 fragments, warp tile 64x64) += A @ B^T, fp16x3.
// BK=64, 2-stage cp.async pipeline. A-fragments streamed per-mt. (R12 exact)
// ---------------------------------------------------------------------------
__device__ __forceinline__ void mma_mainloop(
    const __half* __restrict__ Ah, const __half* __restrict__ Al,
    const __half* __restrict__ Bh, const __half* __restrict__ Bl,
    char* dsm, int rowBase, int colBase, int tid, float acc[4][8][4])
{
    const int lane = tid & 31;
    const int w = tid >> 5, wm = w >> 1, wn = w & 1;
    const uint32_t sbase = smem_u32(dsm);

#pragma unroll
    for (int mt = 0; mt < 4; mt++)
#pragma unroll
        for (int nt = 0; nt < 8; nt++)
#pragma unroll
            for (int q = 0; q < 4; q++) acc[mt][nt][q] = 0.0f;

    const int a_r0 = wm * 64 + (lane & 15);
    const int a_ch = lane >> 4;
    const int b_r0 = wn * 64 + (lane & 7) + ((lane & 16) >> 1);
    const int b_ch = (lane >> 3) & 1;

    auto load_stage = [&](int c, int slot) {
        const int k0 = c * BK;
        const uint32_t sb = sbase + slot * STAGE_BYTES;
#pragma unroll
        for (int i = 0; i < 8; i++) {               // A: 256 rows x 8 ck
            const int id = tid + i * 256;
            const int r = id >> 3, ck = id & 7;
            const uint32_t so = swz(r, ck);
            const size_t ga = (size_t)(rowBase + r) * FF + k0 + ck * 8;
            CP_ASYNC16(sb + OFF_AH + so, Ah + ga);
            CP_ASYNC16(sb + OFF_AL + so, Al + ga);
        }
#pragma unroll
        for (int i = 0; i < 4; i++) {               // B: 128 rows x 8 ck
            const int id = tid + i * 256;
            const int r = id >> 3, ck = id & 7;
            const uint32_t so = swz(r, ck);
            const size_t gb = (size_t)(colBase + r) * FF + k0 + ck * 8;
            CP_ASYNC16(sb + OFF_BH + so, Bh + gb);
            CP_ASYNC16(sb + OFF_BL + so, Bl + gb);
        }
    };

    load_stage(0, 0); CP_COMMIT();

    int s = 0;
    for (int c = 0; c < NCHUNK; c++) {
        if (c + 1 < NCHUNK) {
            load_stage(c + 1, s ^ 1);
            CP_COMMIT();
            CP_WAIT1();          // stage c complete
        } else {
            CP_WAIT0();
        }
        __syncthreads();         // stage c visible to all warps

        const uint32_t sb = sbase + s * STAGE_BYTES;
#pragma unroll
        for (int kk = 0; kk < 4; kk++) {
            // B fragments resident for the whole kk step (32 regs)
            uint32_t bh[4][4], bl[4][4];
#pragma unroll
            for (int p = 0; p < 4; p++) {
                const uint32_t so = swz(b_r0 + p * 16, kk * 2 + b_ch);
                ldsm4(bh[p], sb + OFF_BH + so);
                ldsm4(bl[p], sb + OFF_BL + so);
            }
            // A fragments streamed per-mt (8 regs live)
#pragma unroll
            for (int mt = 0; mt < 4; mt++) {
                uint32_t ah[4], al[4];
                const uint32_t so = swz(a_r0 + mt * 16, kk * 2 + a_ch);
                ldsm4(ah, sb + OFF_AH + so);
                ldsm4(al, sb + OFF_AL + so);
#pragma unroll
                for (int nt = 0; nt < 8; nt++) {
                    const int p = nt >> 1, o = (nt & 1) * 2;
                    mma16816(acc[mt][nt], ah, bh[p][o], bh[p][o + 1]);
                    mma16816(acc[mt][nt], ah, bl[p][o], bl[p][o + 1]);
                    mma16816(acc[mt][nt], al, bh[p][o], bh[p][o + 1]);
                }
            }
        }
        __syncthreads();         // all warps done reading stage s before reuse
        s ^= 1;
    }
}

// ---------------------------------------------------------------------------
// Fused GEMM1+GEMM2 (blockIdx.z): z=0 -> kenc fp32; z=1 -> qenc split hi/lo
// ---------------------------------------------------------------------------
__global__ __launch_bounds__(256, 1) void gemm_enc2(
    const __half* __restrict__ A0h, const __half* __restrict__ A0l,
    const __half* __restrict__ B0h, const __half* __restrict__ B0l,
    const float* __restrict__ bias0,
    const __half* __restrict__ A1h, const __half* __restrict__ A1l,
    const __half* __restrict__ B1h, const __half* __restrict__ B1l,
    const float* __restrict__ bias1,
    __half* __restrict__ O1h, __half* __restrict__ O1l)
{
    extern __shared__ __align__(1024) char dsm[];
    const int tid = threadIdx.x;
    const int rowBase = blockIdx.y * BM;
    const int colBase = blockIdx.x * BN;
    const int z = blockIdx.z;

    const __half* Ah = z ? A1h : A0h;
    const __half* Al = z ? A1l : A0l;
    const __half* Bh = z ? B1h : B0h;
    const __half* Bl = z ? B1l : B0l;
    const float* bias = z ? bias1 : bias0;

    float acc[4][8][4];
    mma_mainloop(Ah, Al, Bh, Bl, dsm, rowBase, colBase, tid, acc);

    const int lane = tid & 31;
    const int w = tid >> 5, wm = w >> 1, wn = w & 1;

#pragma unroll
    for (int nt = 0; nt < 8; nt++) {
        const int col0 = colBase + wn * 64 + nt * 8 + 2 * (lane & 3);
        const float2 bb = *(const float2*)&bias[col0];
#pragma unroll
        for (int mt = 0; mt < 4; mt++) {
            const int row0 = rowBase + wm * 64 + mt * 16 + (lane >> 2);
#pragma unroll
            for (int h = 0; h < 2; h++) {
                const int row = row0 + h * 8;
                const float v0 = fmaxf(acc[mt][nt][2 * h]     + bb.x, 0.0f);
                const float v1 = fmaxf(acc[mt][nt][2 * h + 1] + bb.y, 0.0f);
                if (z == 0) {
                    *(float2*)&g_kenc[(size_t)row * FF + col0] = make_float2(v0, v1);
                } else {
                    __half h0 = __float2half_rn(v0), h1 = __float2half_rn(v1);
                    __half l0 = __float2half_rn(v0 - __half2float(h0));
                    __half l1 = __float2half_rn(v1 - __half2float(h1));
                    *(__half2*)&O1h[(size_t)row * FF + col0] = __halves2half2(h0, h1);
                    *(__half2*)&O1l[(size_t)row * FF + col0] = __halves2half2(l0, l1);
                }
            }
        }
    }
}

// ---------------------------------------------------------------------------
// GEMM3: attn = qenc @ Wa^T + ba, fused energy-partial epilogue
// ---------------------------------------------------------------------------
__global__ __launch_bounds__(256, 1) void gemm_energy(
    const __half* __restrict__ Ah, const __half* __restrict__ Al,
    const __half* __restrict__ Bh, const __half* __restrict__ Bl,
    const float* __restrict__ ba)
{
    extern __shared__ __align__(1024) char dsm[];
    const int tid = threadIdx.x;
    const int rowBase = blockIdx.y * BM;
    const int colBase = blockIdx.x * BN;

    float acc[4][8][4];
    mma_mainloop(Ah, Al, Bh, Bl, dsm, rowBase, colBase, tid, acc);

    const int lane = tid & 31;
    const int w = tid >> 5, wm = w >> 1, wn = w & 1;

    float er[4][2];
#pragma unroll
    for (int mt = 0; mt < 4; mt++) { er[mt][0] = 0.0f; er[mt][1] = 0.0f; }

#pragma unroll
    for (int nt = 0; nt < 8; nt++) {
        const int col0 = colBase + wn * 64 + nt * 8 + 2 * (lane & 3);
        const float2 bb = *(const float2*)&ba[col0];
#pragma unroll
        for (int mt = 0; mt < 4; mt++) {
            const int row0 = rowBase + wm * 64 + mt * 16 + (lane >> 2);
#pragma unroll
            for (int h = 0; h < 2; h++) {
                const int row = row0 + h * 8;
                const float2 kk2 = *(const float2*)&g_kenc[(size_t)row * FF + col0];
                const float v0 = acc[mt][nt][2 * h]     + bb.x;
                const float v1 = acc[mt][nt][2 * h + 1] + bb.y;
                er[mt][h] += v0 * kk2.x + v1 * kk2.y;
            }
        }
    }

#pragma unroll
    for (int mt = 0; mt < 4; mt++) {
#pragma unroll
        for (int h = 0; h < 2; h++) {
            er[mt][h] += __shfl_xor_sync(0xffffffffu, er[mt][h], 1);
            er[mt][h] += __shfl_xor_sync(0xffffffffu, er[mt][h], 2);
        }
    }

    float* e_sm = (float*)dsm;   // [2 wn][256 rows]
    __syncthreads();
    if ((lane & 3) == 0) {
        const int rl0 = wm * 64 + (lane >> 2);
#pragma unroll
        for (int mt = 0; mt < 4; mt++) {
            e_sm[wn * 256 + rl0 + mt * 16]     = er[mt][0];
            e_sm[wn * 256 + rl0 + mt * 16 + 8] = er[mt][1];
        }
    }
    __syncthreads();
    if (tid < 256) {
        float e = e_sm[tid] + e_sm[256 + tid];
        g_epart[blockIdx.x * NN + rowBase + tid] = e;
    }
}

// ---------------------------------------------------------------------------
// Parallel energy reduce + max partials: 64 blocks x 1024 threads.
// ---------------------------------------------------------------------------
__global__ __launch_bounds__(1024) void energy_max_part()
{
    __shared__ float red[1024];
    const int t = threadIdx.x;
    const int i = blockIdx.x * 1024 + t;

    float e = 0.0f;
#pragma unroll
    for (int p = 0; p < 8; p++) e += g_epart[p * NN + i];
    g_energy[i] = e;

    red[t] = e;
    __syncthreads();
    for (int s = 512; s > 0; s >>= 1) {
        if (t < s) red[t] = fmaxf(red[t], red[t + s]);
        __syncthreads();
    }
    if (t == 0) g_maxpart[blockIdx.x] = red[0];
}

__global__ __launch_bounds__(64) void energy_max_final()
{
    __shared__ float red[64];
    const int t = threadIdx.x;
    red[t] = g_maxpart[t];
    __syncthreads();
    for (int s = 32; s > 0; s >>= 1) {
        if (t < s) red[t] = fmaxf(red[t], red[t + s]);
        __syncthreads();
    }
    if (t == 0) g_mx[0] = red[0];
}

// ---------------------------------------------------------------------------
// ctx_partial: computes w=exp(e-mx) inline, accumulates value-weighted sums,
// and emits per-block weight sums for the final normalization.
// ---------------------------------------------------------------------------
__global__ __launch_bounds__(256) void ctx_partial(const float* __restrict__ value)
{
    __shared__ float s_w[256];
    __shared__ float red[256];
    const int b = blockIdx.x;
    const int t = threadIdx.x;
    const int rowBase = b * 256;
    const float mx = g_mx[0];

    const float w = expf(g_energy[rowBase + t] - mx);
    s_w[t] = w;
    red[t] = w;
    __syncthreads();
    for (int s = 128; s > 0; s >>= 1) {
        if (t < s) red[t] += red[t + s];
        __syncthreads();
    }
    if (t == 0) g_wsum[b] = red[0];

    float a0 = 0.f, a1 = 0.f, a2 = 0.f, a3 = 0.f;
    for (int r = 0; r < 256; r++) {
        const float wr = s_w[r];
        const float* vr = value + (size_t)(rowBase + r) * FF;
        a0 += wr * vr[t];
        a1 += wr * vr[t + 256];
        a2 += wr * vr[t + 512];
        a3 += wr * vr[t + 768];
    }
    g_ctxpart[b * FF + t]       = a0;
    g_ctxpart[b * FF + t + 256] = a1;
    g_ctxpart[b * FF + t + 512] = a2;
    g_ctxpart[b * FF + t + 768] = a3;
}

__global__ __launch_bounds__(1024) void ctx_reduce(float* __restrict__ out)
{
    __shared__ float red[256];
    const int c = threadIdx.x;

    if (c < 256) red[c] = g_wsum[c];
    __syncthreads();
    for (int s = 128; s > 0; s >>= 1) {
        if (c < s) red[c] += red[c + s];
        __syncthreads();
    }
    const float invZ = 1.0f / red[0];

    float s = 0.0f;
    for (int b = 0; b < 256; b++) s += g_ctxpart[b * FF + c];
    out[c] = s * invZ;
}

// ---------------------------------------------------------------------------
// Launch
// ---------------------------------------------------------------------------
extern "C" void kernel_launch(void* const* d_in, const int* in_sizes, int n_in,
                              void* d_out, int out_size)
{
    const float* key   = (const float*)d_in[0];
    const float* query = (const float*)d_in[1];
    const float* value = (const float*)d_in[2];
    const float* W0    = (const float*)d_in[3];
    const float* b0    = (const float*)d_in[4];
    const float* W1    = (const float*)d_in[5];
    const float* b1    = (const float*)d_in[6];
    const float* Wa    = (const float*)d_in[7];
    const float* ba    = (const float*)d_in[8];
    float* out = (float*)d_out;

    __half *in0h, *in0l, *in1h, *in1l;
    __half *w0h, *w0l, *w1h, *w1l, *wah, *wal;
    __half *qench, *qencl;
    cudaGetSymbolAddress((void**)&in0h, g_in0h);
    cudaGetSymbolAddress((void**)&in0l, g_in0l);
    cudaGetSymbolAddress((void**)&in1h, g_in1h);
    cudaGetSymbolAddress((void**)&in1l, g_in1l);
    cudaGetSymbolAddress((void**)&w0h, g_w0h);
    cudaGetSymbolAddress((void**)&w0l, g_w0l);
    cudaGetSymbolAddress((void**)&w1h, g_w1h);
    cudaGetSymbolAddress((void**)&w1l, g_w1l);
    cudaGetSymbolAddress((void**)&wah, g_wah);
    cudaGetSymbolAddress((void**)&wal, g_wal);
    cudaGetSymbolAddress((void**)&qench, g_qench);
    cudaGetSymbolAddress((void**)&qencl, g_qencl);

    cudaFuncSetAttribute(gemm_enc2, cudaFuncAttributeMaxDynamicSharedMemorySize, DYN_SMEM);
    cudaFuncSetAttribute(gemm_energy, cudaFuncAttributeMaxDynamicSharedMemorySize, DYN_SMEM);

    const int n4_in = NN * FF / 4;   // 16M float4
    const int n4_w  = FF * FF / 4;   // 256K float4

    // inputs: query (y=0), key (y=1) in one launch
    {
        dim3 g(n4_in / 2048, 2);
        split_batch<<<g, 256>>>(
            (const float4*)query, (uint4*)in0h, (uint4*)in0l,
            (const float4*)key,   (uint4*)in1h, (uint4*)in1l,
            (const float4*)key,   (uint4*)in1h, (uint4*)in1l);  // y=2 unused
    }
    // weights: W0 (y=0), W1 (y=1), Wa (y=2) in one launch
    {
        dim3 g(n4_w / 2048, 3);
        split_batch<<<g, 256>>>(
            (const float4*)W0, (uint4*)w0h, (uint4*)w0l,
            (const float4*)W1, (uint4*)w1h, (uint4*)w1l,
            (const float4*)Wa, (uint4*)wah, (uint4*)wal);
    }

    dim3 grid2(FF / BN, NN / BM, 2);   // (8, 256, 2)
    gemm_enc2<<<grid2, 256, DYN_SMEM>>>(
        in0h, in0l, w0h, w0l, b0,
        in1h, in1l, w1h, w1l, b1, qench, qencl);

    dim3 grid(FF / BN, NN / BM);       // (8, 256)
    gemm_energy<<<grid, 256, DYN_SMEM>>>(qench, qencl, wah, wal, ba);
    energy_max_part<<<64, 1024>>>();
    energy_max_final<<<1, 64>>>();
    ctx_partial<<<256, 256>>>(value);
    ctx_reduce<<<1, 1024>>>(out);
}

// round 15
// speedup vs baseline: 1.1107x; 1.0014x over previous
#include <cuda_runtime.h>
#include <cuda_fp16.h>
#include <math.h>
#include <stdint.h>

#define NN 65536
#define FF 1024
#define BK 64
#define NCHUNK (FF / BK)     // 16
#define BM 256               // CTA rows
#define BN 128               // CTA cols

// per-stage smem: A hi/lo (256x64 halfs = 32KB each), B hi/lo (128x64 = 16KB each)
#define OFF_AH 0
#define OFF_AL 32768
#define OFF_BH 65536
#define OFF_BL 81920
#define STAGE_BYTES 98304
#define DYN_SMEM (2 * STAGE_BYTES)   // 192 KB, 2-stage

// ---------------------------------------------------------------------------
// Device scratch
// ---------------------------------------------------------------------------
__device__ __half g_in0h[(size_t)NN * FF], g_in0l[(size_t)NN * FF]; // query split
__device__ __half g_in1h[(size_t)NN * FF], g_in1l[(size_t)NN * FF]; // key split
__device__ __half g_w0h[FF * FF], g_w0l[FF * FF];
__device__ __half g_w1h[FF * FF], g_w1l[FF * FF];
__device__ __half g_wah[FF * FF], g_wal[FF * FF];
__device__ float  g_kenc[(size_t)NN * FF];                      // fp32 k_enc
__device__ __half g_qench[(size_t)NN * FF], g_qencl[(size_t)NN * FF];
__device__ float  g_epart[8 * NN];
__device__ float  g_energy[NN];
__device__ float  g_maxpart[64];
__device__ float  g_mx[1];
__device__ float  g_wsum[256];
__device__ float  g_ctxpart[256 * FF];

// ---------------------------------------------------------------------------
// PTX helpers (sm_80-class, arch-generic)
// ---------------------------------------------------------------------------
__device__ __forceinline__ uint32_t smem_u32(const void* p) {
    uint32_t a;
    asm("{ .reg .u64 t; cvta.to.shared.u64 t, %1; cvt.u32.u64 %0, t; }"
        : "=r"(a) : "l"(p));
    return a;
}

#define CP_ASYNC16(saddr, gptr) \
    asm volatile("cp.async.cg.shared.global [%0], [%1], 16;" \
                 :: "r"(saddr), "l"(gptr))
#define CP_COMMIT() asm volatile("cp.async.commit_group;" ::: "memory")
#define CP_WAIT0()  asm volatile("cp.async.wait_group 0;" ::: "memory")
#define CP_WAIT1()  asm volatile("cp.async.wait_group 1;" ::: "memory")

__device__ __forceinline__ void ldsm4(uint32_t* r, uint32_t a) {
    asm volatile("ldmatrix.sync.aligned.m8n8.x4.shared.b16 {%0,%1,%2,%3}, [%4];"
                 : "=r"(r[0]), "=r"(r[1]), "=r"(r[2]), "=r"(r[3]) : "r"(a));
}

__device__ __forceinline__ void mma16816(float* d, const uint32_t* a,
                                         uint32_t b0, uint32_t b1) {
    asm volatile(
        "mma.sync.aligned.m16n8k16.row.col.f32.f16.f16.f32 "
        "{%0,%1,%2,%3}, {%4,%5,%6,%7}, {%8,%9}, {%0,%1,%2,%3};"
        : "+f"(d[0]), "+f"(d[1]), "+f"(d[2]), "+f"(d[3])
        : "r"(a[0]), "r"(a[1]), "r"(a[2]), "r"(a[3]), "r"(b0), "r"(b1));
}

// 128B rows (8 chunks of 16B): chunk' = c ^ (r&7); conflict-free ldmatrix.
__device__ __forceinline__ uint32_t swz(int r, int c) {
    return (uint32_t)(r * 128 + ((c ^ (r & 7)) << 4));
}

__device__ __forceinline__ uint32_t pack_hi2(float a, float b) {
    __half2 h = __halves2half2(__float2half_rn(a), __float2half_rn(b));
    return *(uint32_t*)&h;
}
__device__ __forceinline__ uint32_t pack_lo2(float a, float b) {
    __half ha = __float2half_rn(a), hb = __float2half_rn(b);
    __half2 l = __halves2half2(__float2half_rn(a - __half2float(ha)),
                               __float2half_rn(b - __half2float(hb)));
    return *(uint32_t*)&l;
}

// ---------------------------------------------------------------------------
// Single split launch: y=0 -> query, y=1 -> key, y=2 -> {W0,W1,Wa} by x-range.
// Each block converts 2048 float4 (256 thr x 4 uint4-pairs).
// Weights: FF*FF/4 = 262144 float4 = 128 blocks EACH -> y=2 uses x in [0,384).
// ---------------------------------------------------------------------------
__global__ __launch_bounds__(256) void split_all(
    const float4* __restrict__ q,  uint4* __restrict__ qh, uint4* __restrict__ ql,
    const float4* __restrict__ k,  uint4* __restrict__ kh, uint4* __restrict__ kl,
    const float4* __restrict__ w0, uint4* __restrict__ w0h, uint4* __restrict__ w0l,
    const float4* __restrict__ w1, uint4* __restrict__ w1h, uint4* __restrict__ w1l,
    const float4* __restrict__ wa, uint4* __restrict__ wah, uint4* __restrict__ wal)
{
    const float4* x;
    uint4 *hi, *lo;
    int xb = blockIdx.x;

    if (blockIdx.y == 0) {
        x = q; hi = qh; lo = ql;
    } else if (blockIdx.y == 1) {
        x = k; hi = kh; lo = kl;
    } else {
        if (xb >= 384) return;               // weights: 3 x 128 blocks
        if (xb < 128)      { x = w0; hi = w0h; lo = w0l; }
        else if (xb < 256) { x = w1; hi = w1h; lo = w1l; xb -= 128; }
        else               { x = wa; hi = wah; lo = wal; xb -= 256; }
    }

    const int kbase = xb * 1024 + threadIdx.x;   // uint4 index base
#pragma unroll
    for (int j = 0; j < 4; j++) {
        const int idx = kbase + j * 256;
        const float4 v0 = x[2 * idx], v1 = x[2 * idx + 1];
        uint4 hh, ll;
        hh.x = pack_hi2(v0.x, v0.y); hh.y = pack_hi2(v0.z, v0.w);
        hh.z = pack_hi2(v1.x, v1.y); hh.w = pack_hi2(v1.z, v1.w);
        ll.x = pack_lo2(v0.x, v0.y); ll.y = pack_lo2(v0.z, v0.w);
        ll.z = pack_lo2(v1.x, v1.y); ll.w = pack_lo2(v1.z, v1.w);
        hi[idx] = hh;
        lo[idx] = ll;
    }
}

// ---------------------------------------------------------------------------
// Mainloop: acc(256x128 fp32 fragments, warp tile 64x64) += A @ B^T, fp16x3.
// BK=64, 2-stage cp.async pipeline. A-fragments streamed per-mt. (R12 exact)
// ---------------------------------------------------------------------------
__device__ __forceinline__ void mma_mainloop(
    const __half* __restrict__ Ah, const __half* __restrict__ Al,
    const __half* __restrict__ Bh, const __half* __restrict__ Bl,
    char* dsm, int rowBase, int colBase, int tid, float acc[4][8][4])
{
    const int lane = tid & 31;
    const int w = tid >> 5, wm = w >> 1, wn = w & 1;
    const uint32_t sbase = smem_u32(dsm);

#pragma unroll
    for (int mt = 0; mt < 4; mt++)
#pragma unroll
        for (int nt = 0; nt < 8; nt++)
#pragma unroll
            for (int q = 0; q < 4; q++) acc[mt][nt][q] = 0.0f;

    const int a_r0 = wm * 64 + (lane & 15);
    const int a_ch = lane >> 4;
    const int b_r0 = wn * 64 + (lane & 7) + ((lane & 16) >> 1);
    const int b_ch = (lane >> 3) & 1;

    auto load_stage = [&](int c, int slot) {
        const int k0 = c * BK;
        const uint32_t sb = sbase + slot * STAGE_BYTES;
#pragma unroll
        for (int i = 0; i < 8; i++) {               // A: 256 rows x 8 ck
            const int id = tid + i * 256;
            const int r = id >> 3, ck = id & 7;
            const uint32_t so = swz(r, ck);
            const size_t ga = (size_t)(rowBase + r) * FF + k0 + ck * 8;
            CP_ASYNC16(sb + OFF_AH + so, Ah + ga);
            CP_ASYNC16(sb + OFF_AL + so, Al + ga);
        }
#pragma unroll
        for (int i = 0; i < 4; i++) {               // B: 128 rows x 8 ck
            const int id = tid + i * 256;
            const int r = id >> 3, ck = id & 7;
            const uint32_t so = swz(r, ck);
            const size_t gb = (size_t)(colBase + r) * FF + k0 + ck * 8;
            CP_ASYNC16(sb + OFF_BH + so, Bh + gb);
            CP_ASYNC16(sb + OFF_BL + so, Bl + gb);
        }
    };

    load_stage(0, 0); CP_COMMIT();

    int s = 0;
    for (int c = 0; c < NCHUNK; c++) {
        if (c + 1 < NCHUNK) {
            load_stage(c + 1, s ^ 1);
            CP_COMMIT();
            CP_WAIT1();          // stage c complete
        } else {
            CP_WAIT0();
        }
        __syncthreads();         // stage c visible to all warps

        const uint32_t sb = sbase + s * STAGE_BYTES;
#pragma unroll
        for (int kk = 0; kk < 4; kk++) {
            // B fragments resident for the whole kk step (32 regs)
            uint32_t bh[4][4], bl[4][4];
#pragma unroll
            for (int p = 0; p < 4; p++) {
                const uint32_t so = swz(b_r0 + p * 16, kk * 2 + b_ch);
                ldsm4(bh[p], sb + OFF_BH + so);
                ldsm4(bl[p], sb + OFF_BL + so);
            }
            // A fragments streamed per-mt (8 regs live)
#pragma unroll
            for (int mt = 0; mt < 4; mt++) {
                uint32_t ah[4], al[4];
                const uint32_t so = swz(a_r0 + mt * 16, kk * 2 + a_ch);
                ldsm4(ah, sb + OFF_AH + so);
                ldsm4(al, sb + OFF_AL + so);
#pragma unroll
                for (int nt = 0; nt < 8; nt++) {
                    const int p = nt >> 1, o = (nt & 1) * 2;
                    mma16816(acc[mt][nt], ah, bh[p][o], bh[p][o + 1]);
                    mma16816(acc[mt][nt], ah, bl[p][o], bl[p][o + 1]);
                    mma16816(acc[mt][nt], al, bh[p][o], bh[p][o + 1]);
                }
            }
        }
        __syncthreads();         // all warps done reading stage s before reuse
        s ^= 1;
    }
}

// ---------------------------------------------------------------------------
// Fused GEMM1+GEMM2 (blockIdx.z): z=0 -> kenc fp32; z=1 -> qenc split hi/lo
// ---------------------------------------------------------------------------
__global__ __launch_bounds__(256, 1) void gemm_enc2(
    const __half* __restrict__ A0h, const __half* __restrict__ A0l,
    const __half* __restrict__ B0h, const __half* __restrict__ B0l,
    const float* __restrict__ bias0,
    const __half* __restrict__ A1h, const __half* __restrict__ A1l,
    const __half* __restrict__ B1h, const __half* __restrict__ B1l,
    const float* __restrict__ bias1,
    __half* __restrict__ O1h, __half* __restrict__ O1l)
{
    extern __shared__ __align__(1024) char dsm[];
    const int tid = threadIdx.x;
    const int rowBase = blockIdx.y * BM;
    const int colBase = blockIdx.x * BN;
    const int z = blockIdx.z;

    const __half* Ah = z ? A1h : A0h;
    const __half* Al = z ? A1l : A0l;
    const __half* Bh = z ? B1h : B0h;
    const __half* Bl = z ? B1l : B0l;
    const float* bias = z ? bias1 : bias0;

    float acc[4][8][4];
    mma_mainloop(Ah, Al, Bh, Bl, dsm, rowBase, colBase, tid, acc);

    const int lane = tid & 31;
    const int w = tid >> 5, wm = w >> 1, wn = w & 1;

#pragma unroll
    for (int nt = 0; nt < 8; nt++) {
        const int col0 = colBase + wn * 64 + nt * 8 + 2 * (lane & 3);
        const float2 bb = *(const float2*)&bias[col0];
#pragma unroll
        for (int mt = 0; mt < 4; mt++) {
            const int row0 = rowBase + wm * 64 + mt * 16 + (lane >> 2);
#pragma unroll
            for (int h = 0; h < 2; h++) {
                const int row = row0 + h * 8;
                const float v0 = fmaxf(acc[mt][nt][2 * h]     + bb.x, 0.0f);
                const float v1 = fmaxf(acc[mt][nt][2 * h + 1] + bb.y, 0.0f);
                if (z == 0) {
                    *(float2*)&g_kenc[(size_t)row * FF + col0] = make_float2(v0, v1);
                } else {
                    __half h0 = __float2half_rn(v0), h1 = __float2half_rn(v1);
                    __half l0 = __float2half_rn(v0 - __half2float(h0));
                    __half l1 = __float2half_rn(v1 - __half2float(h1));
                    *(__half2*)&O1h[(size_t)row * FF + col0] = __halves2half2(h0, h1);
                    *(__half2*)&O1l[(size_t)row * FF + col0] = __halves2half2(l0, l1);
                }
            }
        }
    }
}

// ---------------------------------------------------------------------------
// GEMM3: attn = qenc @ Wa^T + ba, fused energy-partial epilogue
// ---------------------------------------------------------------------------
__global__ __launch_bounds__(256, 1) void gemm_energy(
    const __half* __restrict__ Ah, const __half* __restrict__ Al,
    const __half* __restrict__ Bh, const __half* __restrict__ Bl,
    const float* __restrict__ ba)
{
    extern __shared__ __align__(1024) char dsm[];
    const int tid = threadIdx.x;
    const int rowBase = blockIdx.y * BM;
    const int colBase = blockIdx.x * BN;

    float acc[4][8][4];
    mma_mainloop(Ah, Al, Bh, Bl, dsm, rowBase, colBase, tid, acc);

    const int lane = tid & 31;
    const int w = tid >> 5, wm = w >> 1, wn = w & 1;

    float er[4][2];
#pragma unroll
    for (int mt = 0; mt < 4; mt++) { er[mt][0] = 0.0f; er[mt][1] = 0.0f; }

#pragma unroll
    for (int nt = 0; nt < 8; nt++) {
        const int col0 = colBase + wn * 64 + nt * 8 + 2 * (lane & 3);
        const float2 bb = *(const float2*)&ba[col0];
#pragma unroll
        for (int mt = 0; mt < 4; mt++) {
            const int row0 = rowBase + wm * 64 + mt * 16 + (lane >> 2);
#pragma unroll
            for (int h = 0; h < 2; h++) {
                const int row = row0 + h * 8;
                const float2 kk2 = *(const float2*)&g_kenc[(size_t)row * FF + col0];
                const float v0 = acc[mt][nt][2 * h]     + bb.x;
                const float v1 = acc[mt][nt][2 * h + 1] + bb.y;
                er[mt][h] += v0 * kk2.x + v1 * kk2.y;
            }
        }
    }

#pragma unroll
    for (int mt = 0; mt < 4; mt++) {
#pragma unroll
        for (int h = 0; h < 2; h++) {
            er[mt][h] += __shfl_xor_sync(0xffffffffu, er[mt][h], 1);
            er[mt][h] += __shfl_xor_sync(0xffffffffu, er[mt][h], 2);
        }
    }

    float* e_sm = (float*)dsm;   // [2 wn][256 rows]
    __syncthreads();
    if ((lane & 3) == 0) {
        const int rl0 = wm * 64 + (lane >> 2);
#pragma unroll
        for (int mt = 0; mt < 4; mt++) {
            e_sm[wn * 256 + rl0 + mt * 16]     = er[mt][0];
            e_sm[wn * 256 + rl0 + mt * 16 + 8] = er[mt][1];
        }
    }
    __syncthreads();
    if (tid < 256) {
        float e = e_sm[tid] + e_sm[256 + tid];
        g_epart[blockIdx.x * NN + rowBase + tid] = e;
    }
}

// ---------------------------------------------------------------------------
// Parallel energy reduce + max partials: 64 blocks x 1024 threads.
// ---------------------------------------------------------------------------
__global__ __launch_bounds__(1024) void energy_max_part()
{
    __shared__ float red[1024];
    const int t = threadIdx.x;
    const int i = blockIdx.x * 1024 + t;

    float e = 0.0f;
#pragma unroll
    for (int p = 0; p < 8; p++) e += g_epart[p * NN + i];
    g_energy[i] = e;

    red[t] = e;
    __syncthreads();
    for (int s = 512; s > 0; s >>= 1) {
        if (t < s) red[t] = fmaxf(red[t], red[t + s]);
        __syncthreads();
    }
    if (t == 0) g_maxpart[blockIdx.x] = red[0];
}

__global__ __launch_bounds__(64) void energy_max_final()
{
    __shared__ float red[64];
    const int t = threadIdx.x;
    red[t] = g_maxpart[t];
    __syncthreads();
    for (int s = 32; s > 0; s >>= 1) {
        if (t < s) red[t] = fmaxf(red[t], red[t + s]);
        __syncthreads();
    }
    if (t == 0) g_mx[0] = red[0];
}

// ---------------------------------------------------------------------------
// ctx_partial: w=exp(e-mx) inline; float4 accumulation (thread t -> cols 4t..4t+3)
// ---------------------------------------------------------------------------
__global__ __launch_bounds__(256) void ctx_partial(const float* __restrict__ value)
{
    __shared__ float s_w[256];
    __shared__ float red[256];
    const int b = blockIdx.x;
    const int t = threadIdx.x;
    const int rowBase = b * 256;
    const float mx = g_mx[0];

    const float w = expf(g_energy[rowBase + t] - mx);
    s_w[t] = w;
    red[t] = w;
    __syncthreads();
    for (int s = 128; s > 0; s >>= 1) {
        if (t < s) red[t] += red[t + s];
        __syncthreads();
    }
    if (t == 0) g_wsum[b] = red[0];

    const float4* v4 = (const float4*)value;    // FF/4 = 256 float4 per row
    float4 acc = make_float4(0.f, 0.f, 0.f, 0.f);
#pragma unroll 2
    for (int r = 0; r < 256; r += 2) {
        const float w0 = s_w[r], w1 = s_w[r + 1];
        const float4 x0 = v4[(size_t)(rowBase + r) * 256 + t];
        const float4 x1 = v4[(size_t)(rowBase + r + 1) * 256 + t];
        acc.x += w0 * x0.x; acc.y += w0 * x0.y;
        acc.z += w0 * x0.z; acc.w += w0 * x0.w;
        acc.x += w1 * x1.x; acc.y += w1 * x1.y;
        acc.z += w1 * x1.z; acc.w += w1 * x1.w;
    }
    ((float4*)g_ctxpart)[b * 256 + t] = acc;
}

// ---------------------------------------------------------------------------
// ctx_reduce: Z from block sums, then float4 column sums over 256 partials.
// ---------------------------------------------------------------------------
__global__ __launch_bounds__(256) void ctx_reduce(float* __restrict__ out)
{
    __shared__ float red[256];
    const int c = threadIdx.x;   // 256 threads, thread c -> cols 4c..4c+3

    red[c] = g_wsum[c];
    __syncthreads();
    for (int s = 128; s > 0; s >>= 1) {
        if (c < s) red[c] += red[c + s];
        __syncthreads();
    }
    const float invZ = 1.0f / red[0];

    const float4* p4 = (const float4*)g_ctxpart;
    float4 s = make_float4(0.f, 0.f, 0.f, 0.f);
#pragma unroll 4
    for (int b = 0; b < 256; b++) {
        const float4 x = p4[b * 256 + c];
        s.x += x.x; s.y += x.y; s.z += x.z; s.w += x.w;
    }
    s.x *= invZ; s.y *= invZ; s.z *= invZ; s.w *= invZ;
    ((float4*)out)[c] = s;
}

// ---------------------------------------------------------------------------
// Launch
// ---------------------------------------------------------------------------
extern "C" void kernel_launch(void* const* d_in, const int* in_sizes, int n_in,
                              void* d_out, int out_size)
{
    const float* key   = (const float*)d_in[0];
    const float* query = (const float*)d_in[1];
    const float* value = (const float*)d_in[2];
    const float* W0    = (const float*)d_in[3];
    const float* b0    = (const float*)d_in[4];
    const float* W1    = (const float*)d_in[5];
    const float* b1    = (const float*)d_in[6];
    const float* Wa    = (const float*)d_in[7];
    const float* ba    = (const float*)d_in[8];
    float* out = (float*)d_out;

    __half *in0h, *in0l, *in1h, *in1l;
    __half *w0h, *w0l, *w1h, *w1l, *wah, *wal;
    __half *qench, *qencl;
    cudaGetSymbolAddress((void**)&in0h, g_in0h);
    cudaGetSymbolAddress((void**)&in0l, g_in0l);
    cudaGetSymbolAddress((void**)&in1h, g_in1h);
    cudaGetSymbolAddress((void**)&in1l, g_in1l);
    cudaGetSymbolAddress((void**)&w0h, g_w0h);
    cudaGetSymbolAddress((void**)&w0l, g_w0l);
    cudaGetSymbolAddress((void**)&w1h, g_w1h);
    cudaGetSymbolAddress((void**)&w1l, g_w1l);
    cudaGetSymbolAddress((void**)&wah, g_wah);
    cudaGetSymbolAddress((void**)&wal, g_wal);
    cudaGetSymbolAddress((void**)&qench, g_qench);
    cudaGetSymbolAddress((void**)&qencl, g_qencl);

    cudaFuncSetAttribute(gemm_enc2, cudaFuncAttributeMaxDynamicSharedMemorySize, DYN_SMEM);
    cudaFuncSetAttribute(gemm_energy, cudaFuncAttributeMaxDynamicSharedMemorySize, DYN_SMEM);

    // one launch for all 5 splits: y=0 query, y=1 key, y=2 weights (x<384)
    {
        dim3 g(NN * FF / 4 / 2048, 3);   // (8192, 3)
        split_all<<<g, 256>>>(
            (const float4*)query, (uint4*)in0h, (uint4*)in0l,
            (const float4*)key,   (uint4*)in1h, (uint4*)in1l,
            (const float4*)W0, (uint4*)w0h, (uint4*)w0l,
            (const float4*)W1, (uint4*)w1h, (uint4*)w1l,
            (const float4*)Wa, (uint4*)wah, (uint4*)wal);
    }

    dim3 grid2(FF / BN, NN / BM, 2);   // (8, 256, 2)
    gemm_enc2<<<grid2, 256, DYN_SMEM>>>(
        in0h, in0l, w0h, w0l, b0,
        in1h, in1l, w1h, w1l, b1, qench, qencl);

    dim3 grid(FF / BN, NN / BM);       // (8, 256)
    gemm_energy<<<grid, 256, DYN_SMEM>>>(qench, qencl, wah, wal, ba);
    energy_max_part<<<64, 1024>>>();
    energy_max_final<<<1, 64>>>();
    ctx_partial<<<256, 256>>>(value);
    ctx_reduce<<<1, 256>>>(out);
}